// round 6
// baseline (speedup 1.0000x reference)
#include <cuda_runtime.h>
#include <cstdint>

#define BB 4
#define TT 2048
#define DD 512
#define HH 8
#define HS 64

// Pre-rounded (tf32) copies + intermediates (all __device__ globals: alloc-free)
__device__ float g_xr[BB*TT*DD];
__device__ float g_wq[HH*DD*HS];
__device__ float g_wk[HH*DD*HS];
__device__ float g_wv[HH*DD*HS];
__device__ float g_wo[DD*DD];
__device__ float g_q[BB*HH*TT*HS];     // [B,H,T,HS] (tf32 values)
__device__ float g_k[BB*HH*TT*HS];
__device__ float g_v[BB*HH*TT*HS];
__device__ float g_attn[BB*TT*DD];     // [B,T,D]    (tf32 values)

// ---------------------------------------------------------------------------
// helpers
// ---------------------------------------------------------------------------
__device__ __forceinline__ float to_tf32(float x) {
    uint32_t u;
    asm("cvt.rna.tf32.f32 %0, %1;" : "=r"(u) : "f"(x));
    return __uint_as_float(u);
}

__device__ __forceinline__ void mma16n8k8(float c[4], const float a[4],
                                          float b0, float b1) {
    asm volatile(
        "mma.sync.aligned.m16n8k8.row.col.f32.tf32.tf32.f32 "
        "{%0,%1,%2,%3}, {%4,%5,%6,%7}, {%8,%9}, {%0,%1,%2,%3};"
        : "+f"(c[0]), "+f"(c[1]), "+f"(c[2]), "+f"(c[3])
        : "r"(__float_as_uint(a[0])), "r"(__float_as_uint(a[1])),
          "r"(__float_as_uint(a[2])), "r"(__float_as_uint(a[3])),
          "r"(__float_as_uint(b0)),  "r"(__float_as_uint(b1)));
}

__device__ __forceinline__ void cpa16(uint32_t dst, const void* src) {
    asm volatile("cp.async.ca.shared.global [%0], [%1], 16;" :: "r"(dst), "l"(src));
}
__device__ __forceinline__ void cpa_commit() {
    asm volatile("cp.async.commit_group;");
}
__device__ __forceinline__ void cpa_wait0() {
    asm volatile("cp.async.wait_group 0;");
}
__device__ __forceinline__ void cpa_wait1() {
    asm volatile("cp.async.wait_group 1;");
}

// ---------------------------------------------------------------------------
// Prep: round inputs to tf32 once (RNA). Idempotent -> numerics identical.
// ---------------------------------------------------------------------------
__global__ __launch_bounds__(256) void round_x_kernel(const float* __restrict__ x) {
    int i = blockIdx.x * 256 + threadIdx.x;
    float4 v = ((const float4*)x)[i];
    v.x = to_tf32(v.x); v.y = to_tf32(v.y); v.z = to_tf32(v.z); v.w = to_tf32(v.w);
    ((float4*)g_xr)[i] = v;
}

__global__ __launch_bounds__(256) void round_w_kernel(
    const float* __restrict__ Wq, const float* __restrict__ Wk,
    const float* __restrict__ Wv, const float* __restrict__ Wo) {
    int i = blockIdx.x * 256 + threadIdx.x;
    int sel = blockIdx.y;
    const float* src = (sel == 0) ? Wq : (sel == 1) ? Wk : (sel == 2) ? Wv : Wo;
    float* dst = (sel == 0) ? g_wq : (sel == 1) ? g_wk : (sel == 2) ? g_wv : g_wo;
    float4 v = ((const float4*)src)[i];
    v.x = to_tf32(v.x); v.y = to_tf32(v.y); v.z = to_tf32(v.z); v.w = to_tf32(v.w);
    ((float4*)dst)[i] = v;
}

// ---------------------------------------------------------------------------
// Kernel 1: QKV projections, tf32 mma + cp.async double buffer (unchanged R4).
// ---------------------------------------------------------------------------
#define XS_STR 36
#define WS_STR 68
#define XS_BUF (128 * XS_STR)
#define WS_BUF (32 * WS_STR)

__global__ __launch_bounds__(128, 4) void qkv_mma_kernel()
{
    extern __shared__ float sm[];
    float* xs = sm;
    float* ws = sm + 2 * XS_BUF;

    const int tid  = threadIdx.x;
    const int lane = tid & 31;
    const int warp = tid >> 5;
    const int lr   = lane >> 2;
    const int lc   = lane & 3;
    const int m0   = blockIdx.x * 128;
    const int h    = blockIdx.y;
    const int wsel = blockIdx.z;

    const float* X = g_xr;
    const float* W = ((wsel == 0) ? g_wq : (wsel == 1) ? g_wk : g_wv)
                     + (size_t)h * DD * HS;
    float* out = (wsel == 0) ? g_q : (wsel == 1) ? g_k : g_v;

    const uint32_t xs_s = (uint32_t)__cvta_generic_to_shared(xs);
    const uint32_t ws_s = (uint32_t)__cvta_generic_to_shared(ws);

    const int xr = tid >> 3, xc4 = tid & 7;
    const int wk = tid >> 4, we4 = tid & 15;

    #define QKV_ISSUE(chunk, buf) do {                                          \
        int k0_ = (chunk) * 32;                                                 \
        _Pragma("unroll")                                                       \
        for (int it = 0; it < 8; it++) {                                        \
            int r = xr + it * 16;                                               \
            cpa16(xs_s + ((buf) * XS_BUF + r * XS_STR + xc4 * 4) * 4,           \
                  X + (size_t)(m0 + r) * DD + k0_ + xc4 * 4);                   \
        }                                                                       \
        _Pragma("unroll")                                                       \
        for (int it = 0; it < 4; it++) {                                        \
            int kk = wk + it * 8;                                               \
            cpa16(ws_s + ((buf) * WS_BUF + kk * WS_STR + we4 * 4) * 4,          \
                  W + (size_t)(k0_ + kk) * HS + we4 * 4);                       \
        }                                                                       \
    } while (0)

    float acc[2][8][4];
    #pragma unroll
    for (int mi = 0; mi < 2; mi++)
        #pragma unroll
        for (int n = 0; n < 8; n++)
            #pragma unroll
            for (int c = 0; c < 4; c++) acc[mi][n][c] = 0.f;

    QKV_ISSUE(0, 0);
    cpa_commit();

    for (int c = 0; c < 16; c++) {
        int cur = c & 1;
        if (c < 15) { QKV_ISSUE(c + 1, cur ^ 1); cpa_commit(); cpa_wait1(); }
        else        { cpa_wait0(); }
        __syncthreads();

        const float* xb = xs + cur * XS_BUF;
        const float* wb = ws + cur * WS_BUF;
        #pragma unroll
        for (int kk = 0; kk < 4; kk++) {
            float a[2][4];
            #pragma unroll
            for (int mi = 0; mi < 2; mi++) {
                int row = warp * 32 + mi * 16;
                a[mi][0] = xb[(row + lr    ) * XS_STR + kk * 8 + lc    ];
                a[mi][1] = xb[(row + lr + 8) * XS_STR + kk * 8 + lc    ];
                a[mi][2] = xb[(row + lr    ) * XS_STR + kk * 8 + lc + 4];
                a[mi][3] = xb[(row + lr + 8) * XS_STR + kk * 8 + lc + 4];
            }
            #pragma unroll
            for (int n = 0; n < 8; n++) {
                float b0 = wb[(kk * 8 + lc    ) * WS_STR + n * 8 + lr];
                float b1 = wb[(kk * 8 + lc + 4) * WS_STR + n * 8 + lr];
                mma16n8k8(acc[0][n], a[0], b0, b1);
                mma16n8k8(acc[1][n], a[1], b0, b1);
            }
        }
        __syncthreads();
    }

    #pragma unroll
    for (int mi = 0; mi < 2; mi++) {
        #pragma unroll
        for (int half = 0; half < 2; half++) {
            int m = m0 + warp * 32 + mi * 16 + lr + half * 8;
            int bb = m >> 11;
            int t  = m & (TT - 1);
            float* og = out + ((size_t)(bb * HH + h) * TT + t) * HS;
            #pragma unroll
            for (int n = 0; n < 8; n++) {
                *(float2*)(og + n * 8 + 2 * lc) =
                    make_float2(to_tf32(acc[mi][n][half * 2]),
                                to_tf32(acc[mi][n][half * 2 + 1]));
            }
        }
    }
}

// ---------------------------------------------------------------------------
// Kernel 2: flash attention, tf32 mma. 256 thr (8 warps), 1 m-tile/warp,
// 128 q/block, cp.async double-buffered K/V, P via register shuffle.
// Reg cap 128 (launch_bounds 256,2) -> 2 blocks/SM, 16 warps (2x R4 occ).
// dyn smem: Qs[128][68] + Ks[2][64][68] + Vs[2][64][68] = 104448 B
// ---------------------------------------------------------------------------
#define AS_STR 68
#define Q_BUF  (128 * AS_STR)
#define KV_BUF (64 * AS_STR)

__global__ __launch_bounds__(256, 2) void attn_mma_kernel()
{
    extern __shared__ float sm[];
    float* Qs = sm;                       // [128][68]
    float* Ks = sm + Q_BUF;               // [2][64][68]
    float* Vs = sm + Q_BUF + 2 * KV_BUF;  // [2][64][68]

    const int tid  = threadIdx.x;
    const int lane = tid & 31;
    const int warp = tid >> 5;
    const int lr   = lane >> 2;
    const int lc   = lane & 3;
    const int wq   = warp * 16;           // warp's query-row base (8 warps x 16)
    const int bh   = blockIdx.y;
    const int qt0  = blockIdx.x * 128;
    const int src  = (lane & 28) | (lc >> 1);   // quad shfl source (j = lc)
    const int src2 = src + 2;                   // (j = lc + 4)

    const float* qg = g_q + ((size_t)bh * TT + qt0) * HS;
    const float* kg = g_k + (size_t)bh * TT * HS;
    const float* vg = g_v + (size_t)bh * TT * HS;

    const uint32_t qs_s = (uint32_t)__cvta_generic_to_shared(Qs);
    const uint32_t ks_s = (uint32_t)__cvta_generic_to_shared(Ks);
    const uint32_t vs_s = (uint32_t)__cvta_generic_to_shared(Vs);

    const int kvr = tid >> 4, kvc4 = tid & 15;  // 64x16 float4 slots, 4 iters

    #define ATTN_ISSUE_KV(tile, buf) do {                                       \
        int t0_ = (tile) * 64;                                                  \
        _Pragma("unroll")                                                       \
        for (int it = 0; it < 4; it++) {                                        \
            int r = kvr + it * 16;                                              \
            uint32_t off = ((buf) * KV_BUF + r * AS_STR + kvc4 * 4) * 4;        \
            cpa16(ks_s + off, kg + (size_t)(t0_ + r) * HS + kvc4 * 4);          \
            cpa16(vs_s + off, vg + (size_t)(t0_ + r) * HS + kvc4 * 4);          \
        }                                                                       \
    } while (0)

    // prologue: Q + KV tile 0
    {
        #pragma unroll
        for (int it = 0; it < 8; it++) {
            int r = kvr + it * 16;
            cpa16(qs_s + (r * AS_STR + kvc4 * 4) * 4, qg + (size_t)r * HS + kvc4 * 4);
        }
        ATTN_ISSUE_KV(0, 0);
        cpa_commit();
        cpa_wait0();
        __syncthreads();
    }

    // Q fragments, pre-scaled by 1/8 (exact exponent shift on tf32 values)
    float qa[8][4];
    #pragma unroll
    for (int kk = 0; kk < 8; kk++) {
        qa[kk][0] = Qs[(wq + lr    ) * AS_STR + kk * 8 + lc    ] * 0.125f;
        qa[kk][1] = Qs[(wq + lr + 8) * AS_STR + kk * 8 + lc    ] * 0.125f;
        qa[kk][2] = Qs[(wq + lr    ) * AS_STR + kk * 8 + lc + 4] * 0.125f;
        qa[kk][3] = Qs[(wq + lr + 8) * AS_STR + kk * 8 + lc + 4] * 0.125f;
    }

    float o[8][4];
    #pragma unroll
    for (int n = 0; n < 8; n++)
        #pragma unroll
        for (int c = 0; c < 4; c++) o[n][c] = 0.f;

    float mlo = -1e30f, mhi = -1e30f;
    float llo = 0.f,    lhi = 0.f;

    for (int t = 0; t < TT / 64; t++) {
        int cur = t & 1;
        if (t < TT / 64 - 1) { ATTN_ISSUE_KV(t + 1, cur ^ 1); cpa_commit(); cpa_wait1(); }
        else                 { cpa_wait0(); }
        __syncthreads();

        const float* kb = Ks + cur * KV_BUF;
        const float* vb = Vs + cur * KV_BUF;

        // ---- S = Q K^T ----
        float sc[8][4];
        #pragma unroll
        for (int n = 0; n < 8; n++)
            #pragma unroll
            for (int c = 0; c < 4; c++) sc[n][c] = 0.f;

        #pragma unroll
        for (int kk = 0; kk < 8; kk++) {
            #pragma unroll
            for (int n = 0; n < 8; n++) {
                float b0 = kb[(n * 8 + lr) * AS_STR + kk * 8 + lc    ];
                float b1 = kb[(n * 8 + lr) * AS_STR + kk * 8 + lc + 4];
                mma16n8k8(sc[n], qa[kk], b0, b1);
            }
        }

        // ---- online softmax ----
        float mx0 = -1e30f, mx1 = -1e30f;
        #pragma unroll
        for (int n = 0; n < 8; n++) {
            mx0 = fmaxf(mx0, fmaxf(sc[n][0], sc[n][1]));
            mx1 = fmaxf(mx1, fmaxf(sc[n][2], sc[n][3]));
        }
        #pragma unroll
        for (int m = 1; m <= 2; m <<= 1) {
            mx0 = fmaxf(mx0, __shfl_xor_sync(0xffffffffu, mx0, m));
            mx1 = fmaxf(mx1, __shfl_xor_sync(0xffffffffu, mx1, m));
        }
        float mn0 = fmaxf(mlo, mx0);
        float mn1 = fmaxf(mhi, mx1);
        float c0 = __expf(mlo - mn0);
        float c1 = __expf(mhi - mn1);
        mlo = mn0; mhi = mn1;
        llo *= c0; lhi *= c1;
        #pragma unroll
        for (int n = 0; n < 8; n++) {
            o[n][0] *= c0; o[n][1] *= c0;
            o[n][2] *= c1; o[n][3] *= c1;
        }
        #pragma unroll
        for (int n = 0; n < 8; n++) {
            sc[n][0] = __expf(sc[n][0] - mn0);
            sc[n][1] = __expf(sc[n][1] - mn0);
            sc[n][2] = __expf(sc[n][2] - mn1);
            sc[n][3] = __expf(sc[n][3] - mn1);
            llo += sc[n][0] + sc[n][1];
            lhi += sc[n][2] + sc[n][3];
        }
        // round P to tf32 (RNA) before it becomes an mma operand
        #pragma unroll
        for (int n = 0; n < 8; n++)
            #pragma unroll
            for (int c = 0; c < 4; c++)
                sc[n][c] = to_tf32(sc[n][c]);

        // ---- O += P V, P permuted C-frag -> A-frag via quad shuffles ----
        #pragma unroll
        for (int kk = 0; kk < 8; kk++) {
            float pa[4];
            {
                float e0a = __shfl_sync(0xffffffffu, sc[kk][0], src);
                float e0b = __shfl_sync(0xffffffffu, sc[kk][1], src);
                float e1a = __shfl_sync(0xffffffffu, sc[kk][2], src);
                float e1b = __shfl_sync(0xffffffffu, sc[kk][3], src);
                float e2a = __shfl_sync(0xffffffffu, sc[kk][0], src2);
                float e2b = __shfl_sync(0xffffffffu, sc[kk][1], src2);
                float e3a = __shfl_sync(0xffffffffu, sc[kk][2], src2);
                float e3b = __shfl_sync(0xffffffffu, sc[kk][3], src2);
                pa[0] = (lc & 1) ? e0b : e0a;
                pa[1] = (lc & 1) ? e1b : e1a;
                pa[2] = (lc & 1) ? e2b : e2a;
                pa[3] = (lc & 1) ? e3b : e3a;
            }
            #pragma unroll
            for (int n = 0; n < 8; n++) {
                float b0 = vb[(kk * 8 + lc    ) * AS_STR + n * 8 + lr];
                float b1 = vb[(kk * 8 + lc + 4) * AS_STR + n * 8 + lr];
                mma16n8k8(o[n], pa, b0, b1);
            }
        }
        __syncthreads();
    }

    // ---- finalize ----
    #pragma unroll
    for (int m = 1; m <= 2; m <<= 1) {
        llo += __shfl_xor_sync(0xffffffffu, llo, m);
        lhi += __shfl_xor_sync(0xffffffffu, lhi, m);
    }
    float inv_lo = 1.f / llo;
    float inv_hi = 1.f / lhi;

    const int bb = bh / HH;
    const int hh = bh % HH;
    const int row_lo = qt0 + wq + lr;
    float* og_lo = g_attn + ((size_t)bb * TT + row_lo    ) * DD + hh * HS;
    float* og_hi = g_attn + ((size_t)bb * TT + row_lo + 8) * DD + hh * HS;
    #pragma unroll
    for (int n = 0; n < 8; n++) {
        *(float2*)(og_lo + n * 8 + 2 * lc) =
            make_float2(to_tf32(o[n][0] * inv_lo), to_tf32(o[n][1] * inv_lo));
        *(float2*)(og_hi + n * 8 + 2 * lc) =
            make_float2(to_tf32(o[n][2] * inv_hi), to_tf32(o[n][3] * inv_hi));
    }
}

// ---------------------------------------------------------------------------
// Kernel 3: output projection, tf32 mma + cp.async double buffer (unchanged R4).
// ---------------------------------------------------------------------------
__global__ __launch_bounds__(128, 4) void oproj_mma_kernel(
    const float* __restrict__ bo,
    float* __restrict__ out)
{
    extern __shared__ float sm[];
    float* xs = sm;
    float* ws = sm + 2 * XS_BUF;

    const int tid  = threadIdx.x;
    const int lane = tid & 31;
    const int warp = tid >> 5;
    const int lr   = lane >> 2;
    const int lc   = lane & 3;
    const int m0   = blockIdx.x * 128;
    const int n0   = blockIdx.y * 64;

    const float* X = g_attn;
    const float* W = g_wo + n0;

    const uint32_t xs_s = (uint32_t)__cvta_generic_to_shared(xs);
    const uint32_t ws_s = (uint32_t)__cvta_generic_to_shared(ws);

    const int xr = tid >> 3, xc4 = tid & 7;
    const int wk = tid >> 4, we4 = tid & 15;

    #define OP_ISSUE(chunk, buf) do {                                           \
        int k0_ = (chunk) * 32;                                                 \
        _Pragma("unroll")                                                       \
        for (int it = 0; it < 8; it++) {                                        \
            int r = xr + it * 16;                                               \
            cpa16(xs_s + ((buf) * XS_BUF + r * XS_STR + xc4 * 4) * 4,           \
                  X + (size_t)(m0 + r) * DD + k0_ + xc4 * 4);                   \
        }                                                                       \
        _Pragma("unroll")                                                       \
        for (int it = 0; it < 4; it++) {                                        \
            int kk = wk + it * 8;                                               \
            cpa16(ws_s + ((buf) * WS_BUF + kk * WS_STR + we4 * 4) * 4,          \
                  W + (size_t)(k0_ + kk) * DD + we4 * 4);                       \
        }                                                                       \
    } while (0)

    float acc[2][8][4];
    #pragma unroll
    for (int mi = 0; mi < 2; mi++)
        #pragma unroll
        for (int n = 0; n < 8; n++)
            #pragma unroll
            for (int c = 0; c < 4; c++) acc[mi][n][c] = 0.f;

    OP_ISSUE(0, 0);
    cpa_commit();

    for (int c = 0; c < 16; c++) {
        int cur = c & 1;
        if (c < 15) { OP_ISSUE(c + 1, cur ^ 1); cpa_commit(); cpa_wait1(); }
        else        { cpa_wait0(); }
        __syncthreads();

        const float* xb = xs + cur * XS_BUF;
        const float* wb = ws + cur * WS_BUF;
        #pragma unroll
        for (int kk = 0; kk < 4; kk++) {
            float a[2][4];
            #pragma unroll
            for (int mi = 0; mi < 2; mi++) {
                int row = warp * 32 + mi * 16;
                a[mi][0] = xb[(row + lr    ) * XS_STR + kk * 8 + lc    ];
                a[mi][1] = xb[(row + lr + 8) * XS_STR + kk * 8 + lc    ];
                a[mi][2] = xb[(row + lr    ) * XS_STR + kk * 8 + lc + 4];
                a[mi][3] = xb[(row + lr + 8) * XS_STR + kk * 8 + lc + 4];
            }
            #pragma unroll
            for (int n = 0; n < 8; n++) {
                float b0 = wb[(kk * 8 + lc    ) * WS_STR + n * 8 + lr];
                float b1 = wb[(kk * 8 + lc + 4) * WS_STR + n * 8 + lr];
                mma16n8k8(acc[0][n], a[0], b0, b1);
                mma16n8k8(acc[1][n], a[1], b0, b1);
            }
        }
        __syncthreads();
    }

    #pragma unroll
    for (int mi = 0; mi < 2; mi++) {
        #pragma unroll
        for (int half = 0; half < 2; half++) {
            int m = m0 + warp * 32 + mi * 16 + lr + half * 8;
            float* og = out + (size_t)m * DD + n0;
            #pragma unroll
            for (int n = 0; n < 8; n++) {
                float2 bias = *(const float2*)(bo + n0 + n * 8 + 2 * lc);
                *(float2*)(og + n * 8 + 2 * lc) =
                    make_float2(acc[mi][n][half * 2]     + bias.x,
                                acc[mi][n][half * 2 + 1] + bias.y);
            }
        }
    }
}

// ---------------------------------------------------------------------------
extern "C" void kernel_launch(void* const* d_in, const int* in_sizes, int n_in,
                              void* d_out, int out_size)
{
    const float* x  = (const float*)d_in[0];
    const float* Wq = (const float*)d_in[1];
    const float* Wk = (const float*)d_in[2];
    const float* Wv = (const float*)d_in[3];
    const float* Wo = (const float*)d_in[4];
    const float* bo = (const float*)d_in[5];
    float* out = (float*)d_out;

    static bool attr_done = false;
    if (!attr_done) {
        cudaFuncSetAttribute(qkv_mma_kernel,
            cudaFuncAttributeMaxDynamicSharedMemorySize, 2*(XS_BUF+WS_BUF)*4);
        cudaFuncSetAttribute(attn_mma_kernel,
            cudaFuncAttributeMaxDynamicSharedMemorySize, (Q_BUF+4*KV_BUF)*4);
        cudaFuncSetAttribute(oproj_mma_kernel,
            cudaFuncAttributeMaxDynamicSharedMemorySize, 2*(XS_BUF+WS_BUF)*4);
        attr_done = true;
    }

    round_x_kernel<<<(BB*TT*DD/4)/256, 256>>>(x);
    dim3 gw((HH*DD*HS/4)/256, 4);
    round_w_kernel<<<gw, 256>>>(Wq, Wk, Wv, Wo);

    dim3 g1((BB * TT) / 128, HH, 3);
    qkv_mma_kernel<<<g1, 128, 2*(XS_BUF+WS_BUF)*4>>>();

    dim3 g2(TT / 128, BB * HH);
    attn_mma_kernel<<<g2, 256, (Q_BUF+4*KV_BUF)*4>>>();

    dim3 g3((BB * TT) / 128, DD / 64);
    oproj_mma_kernel<<<g3, 128, 2*(XS_BUF+WS_BUF)*4>>>(bo, out);
}

// round 7
// speedup vs baseline: 1.1492x; 1.1492x over previous
#include <cuda_runtime.h>
#include <cstdint>

#define BB 4
#define TT 2048
#define DD 512
#define HH 8
#define HS 64

// Pre-rounded (tf32) copies + intermediates (all __device__ globals: alloc-free)
__device__ float g_xr[BB*TT*DD];
__device__ float g_wq[HH*DD*HS];
__device__ float g_wk[HH*DD*HS];
__device__ float g_wv[HH*DD*HS];
__device__ float g_wo[DD*DD];
__device__ float g_q[BB*HH*TT*HS];     // [B,H,T,HS] (tf32 values)
__device__ float g_k[BB*HH*TT*HS];
__device__ float g_v[BB*HH*TT*HS];
__device__ float g_attn[BB*TT*DD];     // [B,T,D]    (tf32 values)

// ---------------------------------------------------------------------------
// helpers
// ---------------------------------------------------------------------------
__device__ __forceinline__ float to_tf32(float x) {
    uint32_t u;
    asm("cvt.rna.tf32.f32 %0, %1;" : "=r"(u) : "f"(x));
    return __uint_as_float(u);
}

__device__ __forceinline__ void mma16n8k8(float c[4], const float a[4],
                                          float b0, float b1) {
    asm volatile(
        "mma.sync.aligned.m16n8k8.row.col.f32.tf32.tf32.f32 "
        "{%0,%1,%2,%3}, {%4,%5,%6,%7}, {%8,%9}, {%0,%1,%2,%3};"
        : "+f"(c[0]), "+f"(c[1]), "+f"(c[2]), "+f"(c[3])
        : "r"(__float_as_uint(a[0])), "r"(__float_as_uint(a[1])),
          "r"(__float_as_uint(a[2])), "r"(__float_as_uint(a[3])),
          "r"(__float_as_uint(b0)),  "r"(__float_as_uint(b1)));
}

__device__ __forceinline__ void cpa16(uint32_t dst, const void* src) {
    asm volatile("cp.async.ca.shared.global [%0], [%1], 16;" :: "r"(dst), "l"(src));
}
__device__ __forceinline__ void cpa_commit() {
    asm volatile("cp.async.commit_group;");
}
__device__ __forceinline__ void cpa_wait0() {
    asm volatile("cp.async.wait_group 0;");
}
__device__ __forceinline__ void cpa_wait1() {
    asm volatile("cp.async.wait_group 1;");
}

// ---------------------------------------------------------------------------
// Prep: round inputs to tf32 once (RNA). Idempotent -> numerics identical.
// ---------------------------------------------------------------------------
__global__ __launch_bounds__(256) void round_x_kernel(const float* __restrict__ x) {
    int i = blockIdx.x * 256 + threadIdx.x;
    float4 v = ((const float4*)x)[i];
    v.x = to_tf32(v.x); v.y = to_tf32(v.y); v.z = to_tf32(v.z); v.w = to_tf32(v.w);
    ((float4*)g_xr)[i] = v;
}

__global__ __launch_bounds__(256) void round_w_kernel(
    const float* __restrict__ Wq, const float* __restrict__ Wk,
    const float* __restrict__ Wv, const float* __restrict__ Wo) {
    int i = blockIdx.x * 256 + threadIdx.x;
    int sel = blockIdx.y;
    const float* src = (sel == 0) ? Wq : (sel == 1) ? Wk : (sel == 2) ? Wv : Wo;
    float* dst = (sel == 0) ? g_wq : (sel == 1) ? g_wk : (sel == 2) ? g_wv : g_wo;
    float4 v = ((const float4*)src)[i];
    v.x = to_tf32(v.x); v.y = to_tf32(v.y); v.z = to_tf32(v.z); v.w = to_tf32(v.w);
    ((float4*)dst)[i] = v;
}

// ---------------------------------------------------------------------------
// Kernel 1: QKV projections, tf32 mma + cp.async double buffer (unchanged R4).
// ---------------------------------------------------------------------------
#define XS_STR 36
#define WS_STR 68
#define XS_BUF (128 * XS_STR)
#define WS_BUF (32 * WS_STR)

__global__ __launch_bounds__(128, 4) void qkv_mma_kernel()
{
    extern __shared__ float sm[];
    float* xs = sm;
    float* ws = sm + 2 * XS_BUF;

    const int tid  = threadIdx.x;
    const int lane = tid & 31;
    const int warp = tid >> 5;
    const int lr   = lane >> 2;
    const int lc   = lane & 3;
    const int m0   = blockIdx.x * 128;
    const int h    = blockIdx.y;
    const int wsel = blockIdx.z;

    const float* X = g_xr;
    const float* W = ((wsel == 0) ? g_wq : (wsel == 1) ? g_wk : g_wv)
                     + (size_t)h * DD * HS;
    float* out = (wsel == 0) ? g_q : (wsel == 1) ? g_k : g_v;

    const uint32_t xs_s = (uint32_t)__cvta_generic_to_shared(xs);
    const uint32_t ws_s = (uint32_t)__cvta_generic_to_shared(ws);

    const int xr = tid >> 3, xc4 = tid & 7;
    const int wk = tid >> 4, we4 = tid & 15;

    #define QKV_ISSUE(chunk, buf) do {                                          \
        int k0_ = (chunk) * 32;                                                 \
        _Pragma("unroll")                                                       \
        for (int it = 0; it < 8; it++) {                                        \
            int r = xr + it * 16;                                               \
            cpa16(xs_s + ((buf) * XS_BUF + r * XS_STR + xc4 * 4) * 4,           \
                  X + (size_t)(m0 + r) * DD + k0_ + xc4 * 4);                   \
        }                                                                       \
        _Pragma("unroll")                                                       \
        for (int it = 0; it < 4; it++) {                                        \
            int kk = wk + it * 8;                                               \
            cpa16(ws_s + ((buf) * WS_BUF + kk * WS_STR + we4 * 4) * 4,          \
                  W + (size_t)(k0_ + kk) * HS + we4 * 4);                       \
        }                                                                       \
    } while (0)

    float acc[2][8][4];
    #pragma unroll
    for (int mi = 0; mi < 2; mi++)
        #pragma unroll
        for (int n = 0; n < 8; n++)
            #pragma unroll
            for (int c = 0; c < 4; c++) acc[mi][n][c] = 0.f;

    QKV_ISSUE(0, 0);
    cpa_commit();

    for (int c = 0; c < 16; c++) {
        int cur = c & 1;
        if (c < 15) { QKV_ISSUE(c + 1, cur ^ 1); cpa_commit(); cpa_wait1(); }
        else        { cpa_wait0(); }
        __syncthreads();

        const float* xb = xs + cur * XS_BUF;
        const float* wb = ws + cur * WS_BUF;
        #pragma unroll
        for (int kk = 0; kk < 4; kk++) {
            float a[2][4];
            #pragma unroll
            for (int mi = 0; mi < 2; mi++) {
                int row = warp * 32 + mi * 16;
                a[mi][0] = xb[(row + lr    ) * XS_STR + kk * 8 + lc    ];
                a[mi][1] = xb[(row + lr + 8) * XS_STR + kk * 8 + lc    ];
                a[mi][2] = xb[(row + lr    ) * XS_STR + kk * 8 + lc + 4];
                a[mi][3] = xb[(row + lr + 8) * XS_STR + kk * 8 + lc + 4];
            }
            #pragma unroll
            for (int n = 0; n < 8; n++) {
                float b0 = wb[(kk * 8 + lc    ) * WS_STR + n * 8 + lr];
                float b1 = wb[(kk * 8 + lc + 4) * WS_STR + n * 8 + lr];
                mma16n8k8(acc[0][n], a[0], b0, b1);
                mma16n8k8(acc[1][n], a[1], b0, b1);
            }
        }
        __syncthreads();
    }

    #pragma unroll
    for (int mi = 0; mi < 2; mi++) {
        #pragma unroll
        for (int half = 0; half < 2; half++) {
            int m = m0 + warp * 32 + mi * 16 + lr + half * 8;
            int bb = m >> 11;
            int t  = m & (TT - 1);
            float* og = out + ((size_t)(bb * HH + h) * TT + t) * HS;
            #pragma unroll
            for (int n = 0; n < 8; n++) {
                *(float2*)(og + n * 8 + 2 * lc) =
                    make_float2(to_tf32(acc[mi][n][half * 2]),
                                to_tf32(acc[mi][n][half * 2 + 1]));
            }
        }
    }
}

// ---------------------------------------------------------------------------
// Kernel 2: flash attention, tf32 mma. 128 thr (4 warps), 2 m-tiles/warp
// (R4 core: B-fragments amortized over 2 mmas). Occupancy lift vs R4:
//  - Q stays in smem (pre-scaled by 1/8 at staging), A-frags reloaded per
//    k-step -> qa's 64 regs freed.
//  - 32-key KV tiles -> sc halved (32 regs freed), smem 69.6KB.
//  - launch_bounds(128,3): reg cap 170 -> 3 blocks/SM, 12 warps (8 in R4).
// dyn smem: Qs[128][68] + Ks[2][32][68] + Vs[2][32][68] = 69632 B
// ---------------------------------------------------------------------------
#define AS_STR  68
#define Q_BUF   (128 * AS_STR)
#define KV2_BUF (32 * AS_STR)
#define KT2     32

__global__ __launch_bounds__(128, 3) void attn_mma_kernel()
{
    extern __shared__ float sm[];
    float* Qs = sm;                        // [128][68] (scaled by 1/8)
    float* Ks = sm + Q_BUF;                // [2][32][68]
    float* Vs = sm + Q_BUF + 2 * KV2_BUF;  // [2][32][68]

    const int tid  = threadIdx.x;
    const int lane = tid & 31;
    const int warp = tid >> 5;
    const int lr   = lane >> 2;
    const int lc   = lane & 3;
    const int bh   = blockIdx.y;
    const int qt0  = blockIdx.x * 128;
    const int src  = (lane & 28) | (lc >> 1);   // quad shfl source (j = lc)
    const int src2 = src + 2;                   // (j = lc + 4)

    const float* qg = g_q + ((size_t)bh * TT + qt0) * HS;
    const float* kg = g_k + (size_t)bh * TT * HS;
    const float* vg = g_v + (size_t)bh * TT * HS;

    const uint32_t ks_s = (uint32_t)__cvta_generic_to_shared(Ks);
    const uint32_t vs_s = (uint32_t)__cvta_generic_to_shared(Vs);

    const int kvr = tid >> 4, kvc4 = tid & 15;  // 32 rows x 16 float4, 2 iters

    #define ATTN_ISSUE_KV(tile, buf) do {                                       \
        int t0_ = (tile) * KT2;                                                 \
        _Pragma("unroll")                                                       \
        for (int it = 0; it < 4; it++) {                                        \
            int r = kvr + it * 8;                                               \
            uint32_t off = ((buf) * KV2_BUF + r * AS_STR + kvc4 * 4) * 4;       \
            cpa16(ks_s + off, kg + (size_t)(t0_ + r) * HS + kvc4 * 4);          \
            cpa16(vs_s + off, vg + (size_t)(t0_ + r) * HS + kvc4 * 4);          \
        }                                                                       \
    } while (0)

    // prologue: KV tile 0 via cp.async overlapping Q staging (scaled 1/8)
    ATTN_ISSUE_KV(0, 0);
    cpa_commit();
    #pragma unroll
    for (int it = 0; it < 16; it++) {
        int idx = tid + it * 128;
        int r = idx >> 4, c4 = idx & 15;
        float4 v = *(const float4*)(qg + (size_t)r * HS + c4 * 4);
        v.x *= 0.125f; v.y *= 0.125f; v.z *= 0.125f; v.w *= 0.125f;
        *(float4*)&Qs[r * AS_STR + c4 * 4] = v;
    }
    cpa_wait0();
    __syncthreads();

    float o[2][8][4];
    float mm[2][2], ll[2][2];
    #pragma unroll
    for (int mi = 0; mi < 2; mi++) {
        #pragma unroll
        for (int n = 0; n < 8; n++)
            #pragma unroll
            for (int c = 0; c < 4; c++) o[mi][n][c] = 0.f;
        mm[mi][0] = mm[mi][1] = -1e30f;
        ll[mi][0] = ll[mi][1] = 0.f;
    }

    for (int t = 0; t < TT / KT2; t++) {
        int cur = t & 1;
        if (t < TT / KT2 - 1) { ATTN_ISSUE_KV(t + 1, cur ^ 1); cpa_commit(); cpa_wait1(); }
        else                  { cpa_wait0(); }
        __syncthreads();

        const float* kb = Ks + cur * KV2_BUF;
        const float* vb = Vs + cur * KV2_BUF;

        // ---- S = (Q/8) K^T : 4 n-tiles (32 keys) x 8 k-steps ----
        float sc[2][4][4];
        #pragma unroll
        for (int mi = 0; mi < 2; mi++)
            #pragma unroll
            for (int n = 0; n < 4; n++)
                #pragma unroll
                for (int c = 0; c < 4; c++) sc[mi][n][c] = 0.f;

        #pragma unroll
        for (int kk = 0; kk < 8; kk++) {
            float a[2][4];
            #pragma unroll
            for (int mi = 0; mi < 2; mi++) {
                int row = warp * 32 + mi * 16;
                a[mi][0] = Qs[(row + lr    ) * AS_STR + kk * 8 + lc    ];
                a[mi][1] = Qs[(row + lr + 8) * AS_STR + kk * 8 + lc    ];
                a[mi][2] = Qs[(row + lr    ) * AS_STR + kk * 8 + lc + 4];
                a[mi][3] = Qs[(row + lr + 8) * AS_STR + kk * 8 + lc + 4];
            }
            #pragma unroll
            for (int n = 0; n < 4; n++) {
                float b0 = kb[(n * 8 + lr) * AS_STR + kk * 8 + lc    ];
                float b1 = kb[(n * 8 + lr) * AS_STR + kk * 8 + lc + 4];
                mma16n8k8(sc[0][n], a[0], b0, b1);
                mma16n8k8(sc[1][n], a[1], b0, b1);
            }
        }

        // ---- online softmax per m-tile ----
        #pragma unroll
        for (int mi = 0; mi < 2; mi++) {
            float mx0 = -1e30f, mx1 = -1e30f;
            #pragma unroll
            for (int n = 0; n < 4; n++) {
                mx0 = fmaxf(mx0, fmaxf(sc[mi][n][0], sc[mi][n][1]));
                mx1 = fmaxf(mx1, fmaxf(sc[mi][n][2], sc[mi][n][3]));
            }
            #pragma unroll
            for (int m = 1; m <= 2; m <<= 1) {
                mx0 = fmaxf(mx0, __shfl_xor_sync(0xffffffffu, mx0, m));
                mx1 = fmaxf(mx1, __shfl_xor_sync(0xffffffffu, mx1, m));
            }
            float mn0 = fmaxf(mm[mi][0], mx0);
            float mn1 = fmaxf(mm[mi][1], mx1);
            float c0 = __expf(mm[mi][0] - mn0);
            float c1 = __expf(mm[mi][1] - mn1);
            mm[mi][0] = mn0; mm[mi][1] = mn1;
            ll[mi][0] *= c0; ll[mi][1] *= c1;
            #pragma unroll
            for (int n = 0; n < 8; n++) {
                o[mi][n][0] *= c0; o[mi][n][1] *= c0;
                o[mi][n][2] *= c1; o[mi][n][3] *= c1;
            }
            #pragma unroll
            for (int n = 0; n < 4; n++) {
                sc[mi][n][0] = __expf(sc[mi][n][0] - mn0);
                sc[mi][n][1] = __expf(sc[mi][n][1] - mn0);
                sc[mi][n][2] = __expf(sc[mi][n][2] - mn1);
                sc[mi][n][3] = __expf(sc[mi][n][3] - mn1);
                ll[mi][0] += sc[mi][n][0] + sc[mi][n][1];
                ll[mi][1] += sc[mi][n][2] + sc[mi][n][3];
            }
            #pragma unroll
            for (int n = 0; n < 4; n++)
                #pragma unroll
                for (int c = 0; c < 4; c++)
                    sc[mi][n][c] = to_tf32(sc[mi][n][c]);
        }

        // ---- O += P V : 4 k-steps (32 keys) x 8 n-tiles (dims) ----
        #pragma unroll
        for (int kk = 0; kk < 4; kk++) {
            float pa[2][4];
            #pragma unroll
            for (int mi = 0; mi < 2; mi++) {
                float e0a = __shfl_sync(0xffffffffu, sc[mi][kk][0], src);
                float e0b = __shfl_sync(0xffffffffu, sc[mi][kk][1], src);
                float e1a = __shfl_sync(0xffffffffu, sc[mi][kk][2], src);
                float e1b = __shfl_sync(0xffffffffu, sc[mi][kk][3], src);
                float e2a = __shfl_sync(0xffffffffu, sc[mi][kk][0], src2);
                float e2b = __shfl_sync(0xffffffffu, sc[mi][kk][1], src2);
                float e3a = __shfl_sync(0xffffffffu, sc[mi][kk][2], src2);
                float e3b = __shfl_sync(0xffffffffu, sc[mi][kk][3], src2);
                pa[mi][0] = (lc & 1) ? e0b : e0a;
                pa[mi][1] = (lc & 1) ? e1b : e1a;
                pa[mi][2] = (lc & 1) ? e2b : e2a;
                pa[mi][3] = (lc & 1) ? e3b : e3a;
            }
            #pragma unroll
            for (int n = 0; n < 8; n++) {
                float b0 = vb[(kk * 8 + lc    ) * AS_STR + n * 8 + lr];
                float b1 = vb[(kk * 8 + lc + 4) * AS_STR + n * 8 + lr];
                mma16n8k8(o[0][n], pa[0], b0, b1);
                mma16n8k8(o[1][n], pa[1], b0, b1);
            }
        }
        __syncthreads();
    }

    // ---- finalize ----
    #pragma unroll
    for (int mi = 0; mi < 2; mi++)
        #pragma unroll
        for (int half = 0; half < 2; half++)
            #pragma unroll
            for (int m = 1; m <= 2; m <<= 1)
                ll[mi][half] += __shfl_xor_sync(0xffffffffu, ll[mi][half], m);

    const int bb = bh / HH;
    const int hh = bh % HH;
    #pragma unroll
    for (int mi = 0; mi < 2; mi++) {
        #pragma unroll
        for (int half = 0; half < 2; half++) {
            float inv = 1.f / ll[mi][half];
            int row = qt0 + warp * 32 + mi * 16 + lr + half * 8;
            float* og = g_attn + ((size_t)bb * TT + row) * DD + hh * HS;
            #pragma unroll
            for (int n = 0; n < 8; n++) {
                *(float2*)(og + n * 8 + 2 * lc) =
                    make_float2(to_tf32(o[mi][n][half * 2]     * inv),
                                to_tf32(o[mi][n][half * 2 + 1] * inv));
            }
        }
    }
}

// ---------------------------------------------------------------------------
// Kernel 3: output projection, tf32 mma + cp.async double buffer (unchanged R4).
// ---------------------------------------------------------------------------
__global__ __launch_bounds__(128, 4) void oproj_mma_kernel(
    const float* __restrict__ bo,
    float* __restrict__ out)
{
    extern __shared__ float sm[];
    float* xs = sm;
    float* ws = sm + 2 * XS_BUF;

    const int tid  = threadIdx.x;
    const int lane = tid & 31;
    const int warp = tid >> 5;
    const int lr   = lane >> 2;
    const int lc   = lane & 3;
    const int m0   = blockIdx.x * 128;
    const int n0   = blockIdx.y * 64;

    const float* X = g_attn;
    const float* W = g_wo + n0;

    const uint32_t xs_s = (uint32_t)__cvta_generic_to_shared(xs);
    const uint32_t ws_s = (uint32_t)__cvta_generic_to_shared(ws);

    const int xr = tid >> 3, xc4 = tid & 7;
    const int wk = tid >> 4, we4 = tid & 15;

    #define OP_ISSUE(chunk, buf) do {                                           \
        int k0_ = (chunk) * 32;                                                 \
        _Pragma("unroll")                                                       \
        for (int it = 0; it < 8; it++) {                                        \
            int r = xr + it * 16;                                               \
            cpa16(xs_s + ((buf) * XS_BUF + r * XS_STR + xc4 * 4) * 4,           \
                  X + (size_t)(m0 + r) * DD + k0_ + xc4 * 4);                   \
        }                                                                       \
        _Pragma("unroll")                                                       \
        for (int it = 0; it < 4; it++) {                                        \
            int kk = wk + it * 8;                                               \
            cpa16(ws_s + ((buf) * WS_BUF + kk * WS_STR + we4 * 4) * 4,          \
                  W + (size_t)(k0_ + kk) * DD + we4 * 4);                       \
        }                                                                       \
    } while (0)

    float acc[2][8][4];
    #pragma unroll
    for (int mi = 0; mi < 2; mi++)
        #pragma unroll
        for (int n = 0; n < 8; n++)
            #pragma unroll
            for (int c = 0; c < 4; c++) acc[mi][n][c] = 0.f;

    OP_ISSUE(0, 0);
    cpa_commit();

    for (int c = 0; c < 16; c++) {
        int cur = c & 1;
        if (c < 15) { OP_ISSUE(c + 1, cur ^ 1); cpa_commit(); cpa_wait1(); }
        else        { cpa_wait0(); }
        __syncthreads();

        const float* xb = xs + cur * XS_BUF;
        const float* wb = ws + cur * WS_BUF;
        #pragma unroll
        for (int kk = 0; kk < 4; kk++) {
            float a[2][4];
            #pragma unroll
            for (int mi = 0; mi < 2; mi++) {
                int row = warp * 32 + mi * 16;
                a[mi][0] = xb[(row + lr    ) * XS_STR + kk * 8 + lc    ];
                a[mi][1] = xb[(row + lr + 8) * XS_STR + kk * 8 + lc    ];
                a[mi][2] = xb[(row + lr    ) * XS_STR + kk * 8 + lc + 4];
                a[mi][3] = xb[(row + lr + 8) * XS_STR + kk * 8 + lc + 4];
            }
            #pragma unroll
            for (int n = 0; n < 8; n++) {
                float b0 = wb[(kk * 8 + lc    ) * WS_STR + n * 8 + lr];
                float b1 = wb[(kk * 8 + lc + 4) * WS_STR + n * 8 + lr];
                mma16n8k8(acc[0][n], a[0], b0, b1);
                mma16n8k8(acc[1][n], a[1], b0, b1);
            }
        }
        __syncthreads();
    }

    #pragma unroll
    for (int mi = 0; mi < 2; mi++) {
        #pragma unroll
        for (int half = 0; half < 2; half++) {
            int m = m0 + warp * 32 + mi * 16 + lr + half * 8;
            float* og = out + (size_t)m * DD + n0;
            #pragma unroll
            for (int n = 0; n < 8; n++) {
                float2 bias = *(const float2*)(bo + n0 + n * 8 + 2 * lc);
                *(float2*)(og + n * 8 + 2 * lc) =
                    make_float2(acc[mi][n][half * 2]     + bias.x,
                                acc[mi][n][half * 2 + 1] + bias.y);
            }
        }
    }
}

// ---------------------------------------------------------------------------
extern "C" void kernel_launch(void* const* d_in, const int* in_sizes, int n_in,
                              void* d_out, int out_size)
{
    const float* x  = (const float*)d_in[0];
    const float* Wq = (const float*)d_in[1];
    const float* Wk = (const float*)d_in[2];
    const float* Wv = (const float*)d_in[3];
    const float* Wo = (const float*)d_in[4];
    const float* bo = (const float*)d_in[5];
    float* out = (float*)d_out;

    static bool attr_done = false;
    if (!attr_done) {
        cudaFuncSetAttribute(qkv_mma_kernel,
            cudaFuncAttributeMaxDynamicSharedMemorySize, 2*(XS_BUF+WS_BUF)*4);
        cudaFuncSetAttribute(attn_mma_kernel,
            cudaFuncAttributeMaxDynamicSharedMemorySize, (Q_BUF+4*KV2_BUF)*4);
        cudaFuncSetAttribute(oproj_mma_kernel,
            cudaFuncAttributeMaxDynamicSharedMemorySize, 2*(XS_BUF+WS_BUF)*4);
        attr_done = true;
    }

    round_x_kernel<<<(BB*TT*DD/4)/256, 256>>>(x);
    dim3 gw((HH*DD*HS/4)/256, 4);
    round_w_kernel<<<gw, 256>>>(Wq, Wk, Wv, Wo);

    dim3 g1((BB * TT) / 128, HH, 3);
    qkv_mma_kernel<<<g1, 128, 2*(XS_BUF+WS_BUF)*4>>>();

    dim3 g2(TT / 128, BB * HH);
    attn_mma_kernel<<<g2, 128, (Q_BUF+4*KV2_BUF)*4>>>();

    dim3 g3((BB * TT) / 128, DD / 64);
    oproj_mma_kernel<<<g3, 128, 2*(XS_BUF+WS_BUF)*4>>>(bo, out);
}

// round 8
// speedup vs baseline: 1.3663x; 1.1889x over previous
#include <cuda_runtime.h>
#include <cuda_fp16.h>
#include <cstdint>

#define BB 4
#define TT 2048
#define DD 512
#define HH 8
#define HS 64

// Pre-rounded (tf32) copies + intermediates (all __device__ globals: alloc-free)
__device__ float g_xr[BB*TT*DD];
__device__ float g_wq[HH*DD*HS];
__device__ float g_wk[HH*DD*HS];
__device__ float g_wv[HH*DD*HS];
__device__ float g_wo[DD*DD];
__device__ float g_q[BB*HH*TT*HS];     // [B,H,T,HS] (tf32 values)
__device__ float g_k[BB*HH*TT*HS];
__device__ float g_v[BB*HH*TT*HS];     // [B,H,T,HS] fp32 (qkv output)
__device__ __half g_v16[BB*HH*HS*TT];  // [B,H,HS,T] fp16 (transposed for PV)
__device__ float g_attn[BB*TT*DD];     // [B,T,D]    (tf32 values)

// ---------------------------------------------------------------------------
// helpers
// ---------------------------------------------------------------------------
__device__ __forceinline__ float to_tf32(float x) {
    uint32_t u;
    asm("cvt.rna.tf32.f32 %0, %1;" : "=r"(u) : "f"(x));
    return __uint_as_float(u);
}

__device__ __forceinline__ void mma16n8k8(float c[4], const float a[4],
                                          float b0, float b1) {
    asm volatile(
        "mma.sync.aligned.m16n8k8.row.col.f32.tf32.tf32.f32 "
        "{%0,%1,%2,%3}, {%4,%5,%6,%7}, {%8,%9}, {%0,%1,%2,%3};"
        : "+f"(c[0]), "+f"(c[1]), "+f"(c[2]), "+f"(c[3])
        : "r"(__float_as_uint(a[0])), "r"(__float_as_uint(a[1])),
          "r"(__float_as_uint(a[2])), "r"(__float_as_uint(a[3])),
          "r"(__float_as_uint(b0)),  "r"(__float_as_uint(b1)));
}

__device__ __forceinline__ void mma16n8k16_f16(float c[4], const uint32_t a[4],
                                               uint32_t b0, uint32_t b1) {
    asm volatile(
        "mma.sync.aligned.m16n8k16.row.col.f32.f16.f16.f32 "
        "{%0,%1,%2,%3}, {%4,%5,%6,%7}, {%8,%9}, {%0,%1,%2,%3};"
        : "+f"(c[0]), "+f"(c[1]), "+f"(c[2]), "+f"(c[3])
        : "r"(a[0]), "r"(a[1]), "r"(a[2]), "r"(a[3]), "r"(b0), "r"(b1));
}

// pack (lo, hi) into fp16x2 (first PTX source -> upper half)
__device__ __forceinline__ uint32_t pack_half2(float lo, float hi) {
    uint32_t r;
    asm("cvt.rn.f16x2.f32 %0, %1, %2;" : "=r"(r) : "f"(hi), "f"(lo));
    return r;
}

__device__ __forceinline__ void cpa16(uint32_t dst, const void* src) {
    asm volatile("cp.async.ca.shared.global [%0], [%1], 16;" :: "r"(dst), "l"(src));
}
__device__ __forceinline__ void cpa_commit() {
    asm volatile("cp.async.commit_group;");
}
__device__ __forceinline__ void cpa_wait0() {
    asm volatile("cp.async.wait_group 0;");
}
__device__ __forceinline__ void cpa_wait1() {
    asm volatile("cp.async.wait_group 1;");
}

// ---------------------------------------------------------------------------
// Prep: round inputs to tf32 once (RNA). Idempotent -> numerics identical.
// ---------------------------------------------------------------------------
__global__ __launch_bounds__(256) void round_x_kernel(const float* __restrict__ x) {
    int i = blockIdx.x * 256 + threadIdx.x;
    float4 v = ((const float4*)x)[i];
    v.x = to_tf32(v.x); v.y = to_tf32(v.y); v.z = to_tf32(v.z); v.w = to_tf32(v.w);
    ((float4*)g_xr)[i] = v;
}

__global__ __launch_bounds__(256) void round_w_kernel(
    const float* __restrict__ Wq, const float* __restrict__ Wk,
    const float* __restrict__ Wv, const float* __restrict__ Wo) {
    int i = blockIdx.x * 256 + threadIdx.x;
    int sel = blockIdx.y;
    const float* src = (sel == 0) ? Wq : (sel == 1) ? Wk : (sel == 2) ? Wv : Wo;
    float* dst = (sel == 0) ? g_wq : (sel == 1) ? g_wk : (sel == 2) ? g_wv : g_wo;
    float4 v = ((const float4*)src)[i];
    v.x = to_tf32(v.x); v.y = to_tf32(v.y); v.z = to_tf32(v.z); v.w = to_tf32(v.w);
    ((float4*)dst)[i] = v;
}

// ---------------------------------------------------------------------------
// V transpose/convert: g_v [bh][t][e] fp32 -> g_v16 [bh][e][t] fp16.
// grid (TT/64=32, BB*HH=32), block 256.
// ---------------------------------------------------------------------------
__global__ __launch_bounds__(256) void vtrans_kernel() {
    __shared__ __half ts[64][72];   // 72*2=144B row stride (16B-divisible)
    const int tid = threadIdx.x;
    const int bh  = blockIdx.y;
    const int t0  = blockIdx.x * 64;
    const float* vg = g_v + ((size_t)bh * TT + t0) * HS;

    #pragma unroll
    for (int it = 0; it < 4; it++) {
        int idx = tid + it * 256;              // 0..1023
        int t = idx >> 4, e4 = idx & 15;
        float4 v = *(const float4*)(vg + t * HS + e4 * 4);
        ts[e4*4+0][t] = __float2half_rn(v.x);
        ts[e4*4+1][t] = __float2half_rn(v.y);
        ts[e4*4+2][t] = __float2half_rn(v.z);
        ts[e4*4+3][t] = __float2half_rn(v.w);
    }
    __syncthreads();
    __half* og = g_v16 + (size_t)bh * HS * TT + t0;
    #pragma unroll
    for (int it = 0; it < 2; it++) {
        int idx = tid + it * 256;              // 0..511
        int e = idx >> 3, tc = idx & 7;
        uint4 val = *(uint4*)&ts[e][tc * 8];
        *(uint4*)(og + (size_t)e * TT + tc * 8) = val;
    }
}

// ---------------------------------------------------------------------------
// Kernel 1: QKV projections, tf32 mma + cp.async double buffer (unchanged).
// ---------------------------------------------------------------------------
#define XS_STR 36
#define WS_STR 68
#define XS_BUF (128 * XS_STR)
#define WS_BUF (32 * WS_STR)

__global__ __launch_bounds__(128, 4) void qkv_mma_kernel()
{
    extern __shared__ float sm[];
    float* xs = sm;
    float* ws = sm + 2 * XS_BUF;

    const int tid  = threadIdx.x;
    const int lane = tid & 31;
    const int warp = tid >> 5;
    const int lr   = lane >> 2;
    const int lc   = lane & 3;
    const int m0   = blockIdx.x * 128;
    const int h    = blockIdx.y;
    const int wsel = blockIdx.z;

    const float* X = g_xr;
    const float* W = ((wsel == 0) ? g_wq : (wsel == 1) ? g_wk : g_wv)
                     + (size_t)h * DD * HS;
    float* out = (wsel == 0) ? g_q : (wsel == 1) ? g_k : g_v;

    const uint32_t xs_s = (uint32_t)__cvta_generic_to_shared(xs);
    const uint32_t ws_s = (uint32_t)__cvta_generic_to_shared(ws);

    const int xr = tid >> 3, xc4 = tid & 7;
    const int wk = tid >> 4, we4 = tid & 15;

    #define QKV_ISSUE(chunk, buf) do {                                          \
        int k0_ = (chunk) * 32;                                                 \
        _Pragma("unroll")                                                       \
        for (int it = 0; it < 8; it++) {                                        \
            int r = xr + it * 16;                                               \
            cpa16(xs_s + ((buf) * XS_BUF + r * XS_STR + xc4 * 4) * 4,           \
                  X + (size_t)(m0 + r) * DD + k0_ + xc4 * 4);                   \
        }                                                                       \
        _Pragma("unroll")                                                       \
        for (int it = 0; it < 4; it++) {                                        \
            int kk = wk + it * 8;                                               \
            cpa16(ws_s + ((buf) * WS_BUF + kk * WS_STR + we4 * 4) * 4,          \
                  W + (size_t)(k0_ + kk) * HS + we4 * 4);                       \
        }                                                                       \
    } while (0)

    float acc[2][8][4];
    #pragma unroll
    for (int mi = 0; mi < 2; mi++)
        #pragma unroll
        for (int n = 0; n < 8; n++)
            #pragma unroll
            for (int c = 0; c < 4; c++) acc[mi][n][c] = 0.f;

    QKV_ISSUE(0, 0);
    cpa_commit();

    for (int c = 0; c < 16; c++) {
        int cur = c & 1;
        if (c < 15) { QKV_ISSUE(c + 1, cur ^ 1); cpa_commit(); cpa_wait1(); }
        else        { cpa_wait0(); }
        __syncthreads();

        const float* xb = xs + cur * XS_BUF;
        const float* wb = ws + cur * WS_BUF;
        #pragma unroll
        for (int kk = 0; kk < 4; kk++) {
            float a[2][4];
            #pragma unroll
            for (int mi = 0; mi < 2; mi++) {
                int row = warp * 32 + mi * 16;
                a[mi][0] = xb[(row + lr    ) * XS_STR + kk * 8 + lc    ];
                a[mi][1] = xb[(row + lr + 8) * XS_STR + kk * 8 + lc    ];
                a[mi][2] = xb[(row + lr    ) * XS_STR + kk * 8 + lc + 4];
                a[mi][3] = xb[(row + lr + 8) * XS_STR + kk * 8 + lc + 4];
            }
            #pragma unroll
            for (int n = 0; n < 8; n++) {
                float b0 = wb[(kk * 8 + lc    ) * WS_STR + n * 8 + lr];
                float b1 = wb[(kk * 8 + lc + 4) * WS_STR + n * 8 + lr];
                mma16n8k8(acc[0][n], a[0], b0, b1);
                mma16n8k8(acc[1][n], a[1], b0, b1);
            }
        }
        __syncthreads();
    }

    #pragma unroll
    for (int mi = 0; mi < 2; mi++) {
        #pragma unroll
        for (int half = 0; half < 2; half++) {
            int m = m0 + warp * 32 + mi * 16 + lr + half * 8;
            int bb = m >> 11;
            int t  = m & (TT - 1);
            float* og = out + ((size_t)(bb * HH + h) * TT + t) * HS;
            #pragma unroll
            for (int n = 0; n < 8; n++) {
                *(float2*)(og + n * 8 + 2 * lc) =
                    make_float2(to_tf32(acc[mi][n][half * 2]),
                                to_tf32(acc[mi][n][half * 2 + 1]));
            }
        }
    }
}

// ---------------------------------------------------------------------------
// Kernel 2: flash attention. QK^T in tf32 mma (m16n8k8), P*V in fp16 mma
// (m16n8k16): S C-frags convert directly to P A-frags (no transpose), V is
// fp16 [dim][key] in smem so B-frags are single LDS.32.
// 128 thr (4 warps), 2 m-tiles/warp, 32-key double-buffered tiles.
// dyn smem: Qs[128][68]f32 + Ks[2][32][68]f32 + Vs[2][64][40]f16 = 62464 B
// ---------------------------------------------------------------------------
#define AS_STR   68
#define Q_BUF    (128 * AS_STR)
#define KV2_BUF  (32 * AS_STR)
#define VS16_STR 40
#define VS16_BUF (64 * VS16_STR)
#define KT2      32

__global__ __launch_bounds__(128, 3) void attn_mma_kernel()
{
    extern __shared__ float sm[];
    float*  Qs   = sm;                              // [128][68] (scaled 1/8)
    float*  Ks   = sm + Q_BUF;                      // [2][32][68]
    __half* Vs16 = (__half*)(sm + Q_BUF + 2 * KV2_BUF);  // [2][64][40]

    const int tid  = threadIdx.x;
    const int lane = tid & 31;
    const int warp = tid >> 5;
    const int lr   = lane >> 2;
    const int lc   = lane & 3;
    const int bh   = blockIdx.y;
    const int qt0  = blockIdx.x * 128;

    const float*  qg   = g_q + ((size_t)bh * TT + qt0) * HS;
    const float*  kg   = g_k + (size_t)bh * TT * HS;
    const __half* vg16 = g_v16 + (size_t)bh * HS * TT;

    const uint32_t ks_s = (uint32_t)__cvta_generic_to_shared(Ks);
    const uint32_t vs_s = (uint32_t)__cvta_generic_to_shared(Vs16);

    const int kvr = tid >> 4, kvc4 = tid & 15;  // K: 32 rows x 16 float4
    const int ve  = tid >> 2, vkc  = tid & 3;   // V: 64 dims x 4 16B-chunks

    #define ATTN_ISSUE_KV(tile, buf) do {                                       \
        int t0_ = (tile) * KT2;                                                 \
        _Pragma("unroll")                                                       \
        for (int it = 0; it < 4; it++) {                                        \
            int r = kvr + it * 8;                                               \
            cpa16(ks_s + ((buf) * KV2_BUF + r * AS_STR + kvc4 * 4) * 4,         \
                  kg + (size_t)(t0_ + r) * HS + kvc4 * 4);                      \
        }                                                                       \
        _Pragma("unroll")                                                       \
        for (int it = 0; it < 2; it++) {                                        \
            int e = ve + it * 32;                                               \
            cpa16(vs_s + ((buf) * VS16_BUF + e * VS16_STR + vkc * 8) * 2,       \
                  vg16 + (size_t)e * TT + t0_ + vkc * 8);                       \
        }                                                                       \
    } while (0)

    // prologue: KV tile 0 via cp.async overlapping Q staging (scaled 1/8)
    ATTN_ISSUE_KV(0, 0);
    cpa_commit();
    #pragma unroll
    for (int it = 0; it < 16; it++) {
        int idx = tid + it * 128;
        int r = idx >> 4, c4 = idx & 15;
        float4 v = *(const float4*)(qg + (size_t)r * HS + c4 * 4);
        v.x *= 0.125f; v.y *= 0.125f; v.z *= 0.125f; v.w *= 0.125f;
        *(float4*)&Qs[r * AS_STR + c4 * 4] = v;
    }
    cpa_wait0();
    __syncthreads();

    float o[2][8][4];
    float mm[2][2], ll[2][2];
    #pragma unroll
    for (int mi = 0; mi < 2; mi++) {
        #pragma unroll
        for (int n = 0; n < 8; n++)
            #pragma unroll
            for (int c = 0; c < 4; c++) o[mi][n][c] = 0.f;
        mm[mi][0] = mm[mi][1] = -1e30f;
        ll[mi][0] = ll[mi][1] = 0.f;
    }

    for (int t = 0; t < TT / KT2; t++) {
        int cur = t & 1;
        if (t < TT / KT2 - 1) { ATTN_ISSUE_KV(t + 1, cur ^ 1); cpa_commit(); cpa_wait1(); }
        else                  { cpa_wait0(); }
        __syncthreads();

        const float*  kb = Ks + cur * KV2_BUF;
        const __half* vb = Vs16 + cur * VS16_BUF;

        // ---- S = (Q/8) K^T : 4 n-tiles (32 keys) x 8 k-steps, tf32 ----
        float sc[2][4][4];
        #pragma unroll
        for (int mi = 0; mi < 2; mi++)
            #pragma unroll
            for (int n = 0; n < 4; n++)
                #pragma unroll
                for (int c = 0; c < 4; c++) sc[mi][n][c] = 0.f;

        #pragma unroll
        for (int kk = 0; kk < 8; kk++) {
            float a[2][4];
            #pragma unroll
            for (int mi = 0; mi < 2; mi++) {
                int row = warp * 32 + mi * 16;
                a[mi][0] = Qs[(row + lr    ) * AS_STR + kk * 8 + lc    ];
                a[mi][1] = Qs[(row + lr + 8) * AS_STR + kk * 8 + lc    ];
                a[mi][2] = Qs[(row + lr    ) * AS_STR + kk * 8 + lc + 4];
                a[mi][3] = Qs[(row + lr + 8) * AS_STR + kk * 8 + lc + 4];
            }
            #pragma unroll
            for (int n = 0; n < 4; n++) {
                float b0 = kb[(n * 8 + lr) * AS_STR + kk * 8 + lc    ];
                float b1 = kb[(n * 8 + lr) * AS_STR + kk * 8 + lc + 4];
                mma16n8k8(sc[0][n], a[0], b0, b1);
                mma16n8k8(sc[1][n], a[1], b0, b1);
            }
        }

        // ---- online softmax per m-tile ----
        #pragma unroll
        for (int mi = 0; mi < 2; mi++) {
            float mx0 = -1e30f, mx1 = -1e30f;
            #pragma unroll
            for (int n = 0; n < 4; n++) {
                mx0 = fmaxf(mx0, fmaxf(sc[mi][n][0], sc[mi][n][1]));
                mx1 = fmaxf(mx1, fmaxf(sc[mi][n][2], sc[mi][n][3]));
            }
            #pragma unroll
            for (int m = 1; m <= 2; m <<= 1) {
                mx0 = fmaxf(mx0, __shfl_xor_sync(0xffffffffu, mx0, m));
                mx1 = fmaxf(mx1, __shfl_xor_sync(0xffffffffu, mx1, m));
            }
            float mn0 = fmaxf(mm[mi][0], mx0);
            float mn1 = fmaxf(mm[mi][1], mx1);
            float c0 = __expf(mm[mi][0] - mn0);
            float c1 = __expf(mm[mi][1] - mn1);
            mm[mi][0] = mn0; mm[mi][1] = mn1;
            ll[mi][0] *= c0; ll[mi][1] *= c1;
            #pragma unroll
            for (int n = 0; n < 8; n++) {
                o[mi][n][0] *= c0; o[mi][n][1] *= c0;
                o[mi][n][2] *= c1; o[mi][n][3] *= c1;
            }
            #pragma unroll
            for (int n = 0; n < 4; n++) {
                sc[mi][n][0] = __expf(sc[mi][n][0] - mn0);
                sc[mi][n][1] = __expf(sc[mi][n][1] - mn0);
                sc[mi][n][2] = __expf(sc[mi][n][2] - mn1);
                sc[mi][n][3] = __expf(sc[mi][n][3] - mn1);
                ll[mi][0] += sc[mi][n][0] + sc[mi][n][1];
                ll[mi][1] += sc[mi][n][2] + sc[mi][n][3];
            }
        }

        // ---- O += P V : fp16 m16n8k16, 2 k16-steps x 8 n-tiles (dims) ----
        // P A-frags come straight from S C-frags (FA2 layout identity).
        #pragma unroll
        for (int kk = 0; kk < 2; kk++) {
            uint32_t pa[2][4];
            #pragma unroll
            for (int mi = 0; mi < 2; mi++) {
                pa[mi][0] = pack_half2(sc[mi][2*kk  ][0], sc[mi][2*kk  ][1]);
                pa[mi][1] = pack_half2(sc[mi][2*kk  ][2], sc[mi][2*kk  ][3]);
                pa[mi][2] = pack_half2(sc[mi][2*kk+1][0], sc[mi][2*kk+1][1]);
                pa[mi][3] = pack_half2(sc[mi][2*kk+1][2], sc[mi][2*kk+1][3]);
            }
            #pragma unroll
            for (int n = 0; n < 8; n++) {
                const __half* vrow = vb + (n * 8 + lr) * VS16_STR + kk * 16;
                uint32_t b0 = *(const uint32_t*)(vrow + 2 * lc);
                uint32_t b1 = *(const uint32_t*)(vrow + 2 * lc + 8);
                mma16n8k16_f16(o[0][n], pa[0], b0, b1);
                mma16n8k16_f16(o[1][n], pa[1], b0, b1);
            }
        }
        __syncthreads();
    }

    // ---- finalize ----
    #pragma unroll
    for (int mi = 0; mi < 2; mi++)
        #pragma unroll
        for (int half = 0; half < 2; half++)
            #pragma unroll
            for (int m = 1; m <= 2; m <<= 1)
                ll[mi][half] += __shfl_xor_sync(0xffffffffu, ll[mi][half], m);

    const int bb = bh / HH;
    const int hh = bh % HH;
    #pragma unroll
    for (int mi = 0; mi < 2; mi++) {
        #pragma unroll
        for (int half = 0; half < 2; half++) {
            float inv = 1.f / ll[mi][half];
            int row = qt0 + warp * 32 + mi * 16 + lr + half * 8;
            float* og = g_attn + ((size_t)bb * TT + row) * DD + hh * HS;
            #pragma unroll
            for (int n = 0; n < 8; n++) {
                *(float2*)(og + n * 8 + 2 * lc) =
                    make_float2(to_tf32(o[mi][n][half * 2]     * inv),
                                to_tf32(o[mi][n][half * 2 + 1] * inv));
            }
        }
    }
}

// ---------------------------------------------------------------------------
// Kernel 3: output projection, tf32 mma + cp.async double buffer (unchanged).
// ---------------------------------------------------------------------------
__global__ __launch_bounds__(128, 4) void oproj_mma_kernel(
    const float* __restrict__ bo,
    float* __restrict__ out)
{
    extern __shared__ float sm[];
    float* xs = sm;
    float* ws = sm + 2 * XS_BUF;

    const int tid  = threadIdx.x;
    const int lane = tid & 31;
    const int warp = tid >> 5;
    const int lr   = lane >> 2;
    const int lc   = lane & 3;
    const int m0   = blockIdx.x * 128;
    const int n0   = blockIdx.y * 64;

    const float* X = g_attn;
    const float* W = g_wo + n0;

    const uint32_t xs_s = (uint32_t)__cvta_generic_to_shared(xs);
    const uint32_t ws_s = (uint32_t)__cvta_generic_to_shared(ws);

    const int xr = tid >> 3, xc4 = tid & 7;
    const int wk = tid >> 4, we4 = tid & 15;

    #define OP_ISSUE(chunk, buf) do {                                           \
        int k0_ = (chunk) * 32;                                                 \
        _Pragma("unroll")                                                       \
        for (int it = 0; it < 8; it++) {                                        \
            int r = xr + it * 16;                                               \
            cpa16(xs_s + ((buf) * XS_BUF + r * XS_STR + xc4 * 4) * 4,           \
                  X + (size_t)(m0 + r) * DD + k0_ + xc4 * 4);                   \
        }                                                                       \
        _Pragma("unroll")                                                       \
        for (int it = 0; it < 4; it++) {                                        \
            int kk = wk + it * 8;                                               \
            cpa16(ws_s + ((buf) * WS_BUF + kk * WS_STR + we4 * 4) * 4,          \
                  W + (size_t)(k0_ + kk) * DD + we4 * 4);                       \
        }                                                                       \
    } while (0)

    float acc[2][8][4];
    #pragma unroll
    for (int mi = 0; mi < 2; mi++)
        #pragma unroll
        for (int n = 0; n < 8; n++)
            #pragma unroll
            for (int c = 0; c < 4; c++) acc[mi][n][c] = 0.f;

    OP_ISSUE(0, 0);
    cpa_commit();

    for (int c = 0; c < 16; c++) {
        int cur = c & 1;
        if (c < 15) { OP_ISSUE(c + 1, cur ^ 1); cpa_commit(); cpa_wait1(); }
        else        { cpa_wait0(); }
        __syncthreads();

        const float* xb = xs + cur * XS_BUF;
        const float* wb = ws + cur * WS_BUF;
        #pragma unroll
        for (int kk = 0; kk < 4; kk++) {
            float a[2][4];
            #pragma unroll
            for (int mi = 0; mi < 2; mi++) {
                int row = warp * 32 + mi * 16;
                a[mi][0] = xb[(row + lr    ) * XS_STR + kk * 8 + lc    ];
                a[mi][1] = xb[(row + lr + 8) * XS_STR + kk * 8 + lc    ];
                a[mi][2] = xb[(row + lr    ) * XS_STR + kk * 8 + lc + 4];
                a[mi][3] = xb[(row + lr + 8) * XS_STR + kk * 8 + lc + 4];
            }
            #pragma unroll
            for (int n = 0; n < 8; n++) {
                float b0 = wb[(kk * 8 + lc    ) * WS_STR + n * 8 + lr];
                float b1 = wb[(kk * 8 + lc + 4) * WS_STR + n * 8 + lr];
                mma16n8k8(acc[0][n], a[0], b0, b1);
                mma16n8k8(acc[1][n], a[1], b0, b1);
            }
        }
        __syncthreads();
    }

    #pragma unroll
    for (int mi = 0; mi < 2; mi++) {
        #pragma unroll
        for (int half = 0; half < 2; half++) {
            int m = m0 + warp * 32 + mi * 16 + lr + half * 8;
            float* og = out + (size_t)m * DD + n0;
            #pragma unroll
            for (int n = 0; n < 8; n++) {
                float2 bias = *(const float2*)(bo + n0 + n * 8 + 2 * lc);
                *(float2*)(og + n * 8 + 2 * lc) =
                    make_float2(acc[mi][n][half * 2]     + bias.x,
                                acc[mi][n][half * 2 + 1] + bias.y);
            }
        }
    }
}

// ---------------------------------------------------------------------------
extern "C" void kernel_launch(void* const* d_in, const int* in_sizes, int n_in,
                              void* d_out, int out_size)
{
    const float* x  = (const float*)d_in[0];
    const float* Wq = (const float*)d_in[1];
    const float* Wk = (const float*)d_in[2];
    const float* Wv = (const float*)d_in[3];
    const float* Wo = (const float*)d_in[4];
    const float* bo = (const float*)d_in[5];
    float* out = (float*)d_out;

    const int attn_smem = (Q_BUF + 2 * KV2_BUF) * 4 + 2 * VS16_BUF * 2;

    static bool attr_done = false;
    if (!attr_done) {
        cudaFuncSetAttribute(qkv_mma_kernel,
            cudaFuncAttributeMaxDynamicSharedMemorySize, 2*(XS_BUF+WS_BUF)*4);
        cudaFuncSetAttribute(attn_mma_kernel,
            cudaFuncAttributeMaxDynamicSharedMemorySize, attn_smem);
        cudaFuncSetAttribute(oproj_mma_kernel,
            cudaFuncAttributeMaxDynamicSharedMemorySize, 2*(XS_BUF+WS_BUF)*4);
        attr_done = true;
    }

    round_x_kernel<<<(BB*TT*DD/4)/256, 256>>>(x);
    dim3 gw((HH*DD*HS/4)/256, 4);
    round_w_kernel<<<gw, 256>>>(Wq, Wk, Wv, Wo);

    dim3 g1((BB * TT) / 128, HH, 3);
    qkv_mma_kernel<<<g1, 128, 2*(XS_BUF+WS_BUF)*4>>>();

    dim3 gv(TT / 64, BB * HH);
    vtrans_kernel<<<gv, 256>>>();

    dim3 g2(TT / 128, BB * HH);
    attn_mma_kernel<<<g2, 128, attn_smem>>>();

    dim3 g3((BB * TT) / 128, DD / 64);
    oproj_mma_kernel<<<g3, 128, 2*(XS_BUF+WS_BUF)*4>>>(bo, out);
}

// round 14
// speedup vs baseline: 1.4545x; 1.0646x over previous
#include <cuda_runtime.h>
#include <cuda_fp16.h>
#include <cstdint>

#define BB 4
#define TT 2048
#define DD 512
#define HH 8
#define HS 64

// Globals (allocation-free rule). NOTE: device globals are ONLY referenced
// from device code — never passed as kernel arguments from host (that was
// the R8-R12 allocation-guard bug: host-side __device__ symbol decay).
__device__ __half g_x16[BB*TT*DD];       // x, fp16
__device__ __half g_wq16t[HH*HS*DD];     // Wq^T per head: [h][e][d] fp16
__device__ __half g_wk16t[HH*HS*DD];
__device__ __half g_wv16t[HH*HS*DD];
__device__ float  g_wo[DD*DD];           // Wo, fp32 tf32-rounded
__device__ float  g_q[BB*HH*TT*HS];      // [B,H,T,HS] tf32 values
__device__ float  g_k[BB*HH*TT*HS];
__device__ float  g_v[BB*HH*TT*HS];      // fp32 (feeds vtrans)
__device__ __half g_v16[BB*HH*HS*TT];    // [B,H,HS,T] fp16 (PV operand)
__device__ float  g_attn[BB*TT*DD];      // [B,T,D] tf32 values (oproj A)

// ---------------------------------------------------------------------------
// helpers
// ---------------------------------------------------------------------------
__device__ __forceinline__ float to_tf32(float x) {
    uint32_t u;
    asm("cvt.rna.tf32.f32 %0, %1;" : "=r"(u) : "f"(x));
    return __uint_as_float(u);
}

__device__ __forceinline__ void mma16n8k8(float c[4], const float a[4],
                                          float b0, float b1) {
    asm volatile(
        "mma.sync.aligned.m16n8k8.row.col.f32.tf32.tf32.f32 "
        "{%0,%1,%2,%3}, {%4,%5,%6,%7}, {%8,%9}, {%0,%1,%2,%3};"
        : "+f"(c[0]), "+f"(c[1]), "+f"(c[2]), "+f"(c[3])
        : "r"(__float_as_uint(a[0])), "r"(__float_as_uint(a[1])),
          "r"(__float_as_uint(a[2])), "r"(__float_as_uint(a[3])),
          "r"(__float_as_uint(b0)),  "r"(__float_as_uint(b1)));
}

__device__ __forceinline__ void mma16n8k16_f16(float c[4], const uint32_t a[4],
                                               uint32_t b0, uint32_t b1) {
    asm volatile(
        "mma.sync.aligned.m16n8k16.row.col.f32.f16.f16.f32 "
        "{%0,%1,%2,%3}, {%4,%5,%6,%7}, {%8,%9}, {%0,%1,%2,%3};"
        : "+f"(c[0]), "+f"(c[1]), "+f"(c[2]), "+f"(c[3])
        : "r"(a[0]), "r"(a[1]), "r"(a[2]), "r"(a[3]), "r"(b0), "r"(b1));
}

// pack (lo, hi) -> fp16x2 (lo in lower half)
__device__ __forceinline__ uint32_t pack_half2(float lo, float hi) {
    uint32_t r;
    asm("cvt.rn.f16x2.f32 %0, %1, %2;" : "=r"(r) : "f"(hi), "f"(lo));
    return r;
}

__device__ __forceinline__ void cpa16(uint32_t dst, const void* src) {
    asm volatile("cp.async.ca.shared.global [%0], [%1], 16;" :: "r"(dst), "l"(src));
}
__device__ __forceinline__ void cpa_commit() {
    asm volatile("cp.async.commit_group;");
}
__device__ __forceinline__ void cpa_wait0() {
    asm volatile("cp.async.wait_group 0;");
}
__device__ __forceinline__ void cpa_wait1() {
    asm volatile("cp.async.wait_group 1;");
}

// ---------------------------------------------------------------------------
// Prep 1: x fp32 -> fp16 (writes g_x16 from device code)
// ---------------------------------------------------------------------------
__global__ __launch_bounds__(256) void x16_kernel(const float* __restrict__ x) {
    int i = blockIdx.x * 256 + threadIdx.x;    // float4 index
    float4 v = ((const float4*)x)[i];
    uint32_t h0 = pack_half2(v.x, v.y);
    uint32_t h1 = pack_half2(v.z, v.w);
    *(uint2*)(g_x16 + (size_t)i * 4) = make_uint2(h0, h1);
}

// ---------------------------------------------------------------------------
// Prep 2: Wq/Wk/Wv [h][d][e] fp32 -> g_w{q,k,v}16t [h][e][d] fp16.
// Destination selected DEVICE-SIDE from blockIdx.y (no global-as-arg).
// grid (DD/64=8 d-tiles, 3 wsel, HH=8 heads), block 256.
// ---------------------------------------------------------------------------
__global__ __launch_bounds__(256) void wqkv_trans16_kernel(
    const float* __restrict__ Wq, const float* __restrict__ Wk,
    const float* __restrict__ Wv)
{
    __shared__ __half ts[64][72];
    const int tid  = threadIdx.x;
    const int r0   = blockIdx.x * 64;    // d-offset
    const int wsel = blockIdx.y;
    const int h    = blockIdx.z;

    const float* src = ((wsel == 0) ? Wq : (wsel == 1) ? Wk : Wv)
                       + (size_t)h * DD * HS;
    __half* dst = ((wsel == 0) ? g_wq16t : (wsel == 1) ? g_wk16t : g_wv16t)
                  + (size_t)h * HS * DD;

    // load 64 d-rows x 64 e-cols, transpose into ts[e][d]
    #pragma unroll
    for (int it = 0; it < 4; it++) {
        int idx = tid + it * 256;          // 0..1023
        int r = idx >> 4, c4 = idx & 15;   // r: d-row, c4: e float4
        float4 v = *(const float4*)(src + (size_t)(r0 + r) * HS + c4 * 4);
        ts[c4*4+0][r] = __float2half_rn(v.x);
        ts[c4*4+1][r] = __float2half_rn(v.y);
        ts[c4*4+2][r] = __float2half_rn(v.z);
        ts[c4*4+3][r] = __float2half_rn(v.w);
    }
    __syncthreads();
    // store ts[e][0..63] to dst[e*DD + r0 + ...]
    #pragma unroll
    for (int it = 0; it < 2; it++) {
        int idx = tid + it * 256;          // 0..511
        int e = idx >> 3, rc = idx & 7;
        *(uint4*)(dst + (size_t)e * DD + r0 + rc * 8) = *(uint4*)&ts[e][rc * 8];
    }
}

// ---------------------------------------------------------------------------
// Prep 2b: Wo fp32 -> g_wo fp32 tf32-rounded (device-side global write)
// ---------------------------------------------------------------------------
__global__ __launch_bounds__(256) void round_wo_kernel(const float* __restrict__ Wo) {
    int i = blockIdx.x * 256 + threadIdx.x;    // float4 index
    float4 v = ((const float4*)Wo)[i];
    v.x = to_tf32(v.x); v.y = to_tf32(v.y); v.z = to_tf32(v.z); v.w = to_tf32(v.w);
    ((float4*)g_wo)[i] = v;
}

// ---------------------------------------------------------------------------
// Prep 3: V transpose/convert (VERBATIM from R7-passing build)
// ---------------------------------------------------------------------------
__global__ __launch_bounds__(256) void vtrans_kernel() {
    __shared__ __half ts[64][72];
    const int tid = threadIdx.x;
    const int bh  = blockIdx.y;
    const int t0  = blockIdx.x * 64;
    const float* vg = g_v + ((size_t)bh * TT + t0) * HS;

    #pragma unroll
    for (int it = 0; it < 4; it++) {
        int idx = tid + it * 256;
        int t = idx >> 4, e4 = idx & 15;
        float4 v = *(const float4*)(vg + t * HS + e4 * 4);
        ts[e4*4+0][t] = __float2half_rn(v.x);
        ts[e4*4+1][t] = __float2half_rn(v.y);
        ts[e4*4+2][t] = __float2half_rn(v.z);
        ts[e4*4+3][t] = __float2half_rn(v.w);
    }
    __syncthreads();
    __half* og = g_v16 + (size_t)bh * HS * TT + t0;
    #pragma unroll
    for (int it = 0; it < 2; it++) {
        int idx = tid + it * 256;
        int e = idx >> 3, tc = idx & 7;
        *(uint4*)(og + (size_t)e * TT + tc * 8) = *(uint4*)&ts[e][tc * 8];
    }
}

// ---------------------------------------------------------------------------
// Kernel 1: QKV projections, fp16 m16n8k16 (de-risked shape).
// 256 thr (8 warps), 1 m-tile/warp (16 rows x 64 cols), k chunked by 32,
// static smem (30.7 KB), fragment addressing via uint32_t arrays.
// acc = 32 regs/thread; ~80 live -> no spill possible.
// grid (BT/128=64, H=8, 3).
// ---------------------------------------------------------------------------
__global__ __launch_bounds__(256) void qkv_mma_kernel()
{
    __shared__ uint32_t xs[2][128][20];   // 128 rows x 40 halfs (32 data + 8 pad)
    __shared__ uint32_t ws[2][64][20];    // 64 n-rows x 40 halfs

    const int tid  = threadIdx.x;
    const int lane = tid & 31;
    const int warp = tid >> 5;            // 0..7 -> 16-row m-tile each
    const int lr   = lane >> 2;
    const int lc   = lane & 3;
    const int m0   = blockIdx.x * 128;
    const int h    = blockIdx.y;
    const int wsel = blockIdx.z;

    const __half* X16 = g_x16;
    const __half* W16 = ((wsel == 0) ? g_wq16t : (wsel == 1) ? g_wk16t : g_wv16t)
                        + (size_t)h * HS * DD;
    float* out = (wsel == 0) ? g_q : (wsel == 1) ? g_k : g_v;

    // cp.async slots: x = 128 rows x 4 16B-chunks (2/thread); w = 64 x 4 (1/thread)
    const int xr = tid >> 1, xc = (tid & 1) * 2;   // chunks xc, xc+1
    const int wn = tid >> 2, wc = tid & 3;

    #define QKV_ISSUE(chunk, buf) do {                                          \
        int k0_ = (chunk) * 32;                                                 \
        cpa16((uint32_t)__cvta_generic_to_shared(&xs[buf][xr][(xc    ) * 4]),   \
              X16 + (size_t)(m0 + xr) * DD + k0_ + (xc    ) * 8);               \
        cpa16((uint32_t)__cvta_generic_to_shared(&xs[buf][xr][(xc + 1) * 4]),   \
              X16 + (size_t)(m0 + xr) * DD + k0_ + (xc + 1) * 8);               \
        cpa16((uint32_t)__cvta_generic_to_shared(&ws[buf][wn][wc * 4]),         \
              W16 + (size_t)wn * DD + k0_ + wc * 8);                            \
    } while (0)

    float acc[8][4];
    #pragma unroll
    for (int n = 0; n < 8; n++)
        #pragma unroll
        for (int c = 0; c < 4; c++) acc[n][c] = 0.f;

    QKV_ISSUE(0, 0);
    cpa_commit();

    const int row = warp * 16;
    for (int c = 0; c < 16; c++) {
        int cur = c & 1;
        if (c < 15) { QKV_ISSUE(c + 1, cur ^ 1); cpa_commit(); cpa_wait1(); }
        else        { cpa_wait0(); }
        __syncthreads();

        #pragma unroll
        for (int ks = 0; ks < 2; ks++) {       // two k16 steps per k32 chunk
            uint32_t a[4];
            a[0] = xs[cur][row + lr    ][ks * 8 + lc    ];
            a[1] = xs[cur][row + lr + 8][ks * 8 + lc    ];
            a[2] = xs[cur][row + lr    ][ks * 8 + lc + 4];
            a[3] = xs[cur][row + lr + 8][ks * 8 + lc + 4];
            #pragma unroll
            for (int n = 0; n < 8; n++) {
                uint32_t b0 = ws[cur][n * 8 + lr][ks * 8 + lc    ];
                uint32_t b1 = ws[cur][n * 8 + lr][ks * 8 + lc + 4];
                mma16n8k16_f16(acc[n], a, b0, b1);
            }
        }
        __syncthreads();
    }

    // epilogue: write tf32-rounded fp32 (attention QK consumes without cvt)
    #pragma unroll
    for (int half = 0; half < 2; half++) {
        int m = m0 + row + lr + half * 8;
        int bb = m >> 11;
        int t  = m & (TT - 1);
        float* og = out + ((size_t)(bb * HH + h) * TT + t) * HS;
        #pragma unroll
        for (int n = 0; n < 8; n++) {
            *(float2*)(og + n * 8 + 2 * lc) =
                make_float2(to_tf32(acc[n][half * 2]),
                            to_tf32(acc[n][half * 2 + 1]));
        }
    }
}

// ---------------------------------------------------------------------------
// Kernel 2: flash attention — VERBATIM from the R7-passing build.
// QK^T tf32 (m16n8k8), P*V fp16 (m16n8k16). 128 thr, 2 m-tiles/warp,
// 32-key double-buffered tiles. Writes g_attn fp32 (tf32-rounded).
// dyn smem: Qs[128][68]f32 + Ks[2][32][68]f32 + Vs[2][64][40]f16 = 62464 B
// ---------------------------------------------------------------------------
#define AS_STR   68
#define Q_BUF    (128 * AS_STR)
#define KV2_BUF  (32 * AS_STR)
#define VS16_STR 40
#define VS16_BUF (64 * VS16_STR)
#define KT2      32

__global__ __launch_bounds__(128, 3) void attn_mma_kernel()
{
    extern __shared__ float sm[];
    float*  Qs   = sm;                              // [128][68] (scaled 1/8)
    float*  Ks   = sm + Q_BUF;                      // [2][32][68]
    __half* Vs16 = (__half*)(sm + Q_BUF + 2 * KV2_BUF);  // [2][64][40]

    const int tid  = threadIdx.x;
    const int lane = tid & 31;
    const int warp = tid >> 5;
    const int lr   = lane >> 2;
    const int lc   = lane & 3;
    const int bh   = blockIdx.y;
    const int qt0  = blockIdx.x * 128;

    const float*  qg   = g_q + ((size_t)bh * TT + qt0) * HS;
    const float*  kg   = g_k + (size_t)bh * TT * HS;
    const __half* vg16 = g_v16 + (size_t)bh * HS * TT;

    const uint32_t ks_s = (uint32_t)__cvta_generic_to_shared(Ks);
    const uint32_t vs_s = (uint32_t)__cvta_generic_to_shared(Vs16);

    const int kvr = tid >> 4, kvc4 = tid & 15;  // K: 32 rows x 16 float4
    const int ve  = tid >> 2, vkc  = tid & 3;   // V: 64 dims x 4 16B-chunks

    #define ATTN_ISSUE_KV(tile, buf) do {                                       \
        int t0_ = (tile) * KT2;                                                 \
        _Pragma("unroll")                                                       \
        for (int it = 0; it < 4; it++) {                                        \
            int r = kvr + it * 8;                                               \
            cpa16(ks_s + ((buf) * KV2_BUF + r * AS_STR + kvc4 * 4) * 4,         \
                  kg + (size_t)(t0_ + r) * HS + kvc4 * 4);                      \
        }                                                                       \
        _Pragma("unroll")                                                       \
        for (int it = 0; it < 2; it++) {                                        \
            int e = ve + it * 32;                                               \
            cpa16(vs_s + ((buf) * VS16_BUF + e * VS16_STR + vkc * 8) * 2,       \
                  vg16 + (size_t)e * TT + t0_ + vkc * 8);                       \
        }                                                                       \
    } while (0)

    ATTN_ISSUE_KV(0, 0);
    cpa_commit();
    #pragma unroll
    for (int it = 0; it < 16; it++) {
        int idx = tid + it * 128;
        int r = idx >> 4, c4 = idx & 15;
        float4 v = *(const float4*)(qg + (size_t)r * HS + c4 * 4);
        v.x *= 0.125f; v.y *= 0.125f; v.z *= 0.125f; v.w *= 0.125f;
        *(float4*)&Qs[r * AS_STR + c4 * 4] = v;
    }
    cpa_wait0();
    __syncthreads();

    float o[2][8][4];
    float mm[2][2], ll[2][2];
    #pragma unroll
    for (int mi = 0; mi < 2; mi++) {
        #pragma unroll
        for (int n = 0; n < 8; n++)
            #pragma unroll
            for (int c = 0; c < 4; c++) o[mi][n][c] = 0.f;
        mm[mi][0] = mm[mi][1] = -1e30f;
        ll[mi][0] = ll[mi][1] = 0.f;
    }

    for (int t = 0; t < TT / KT2; t++) {
        int cur = t & 1;
        if (t < TT / KT2 - 1) { ATTN_ISSUE_KV(t + 1, cur ^ 1); cpa_commit(); cpa_wait1(); }
        else                  { cpa_wait0(); }
        __syncthreads();

        const float*  kb = Ks + cur * KV2_BUF;
        const __half* vb = Vs16 + cur * VS16_BUF;

        // ---- S = (Q/8) K^T : 4 n-tiles (32 keys) x 8 k-steps, tf32 ----
        float sc[2][4][4];
        #pragma unroll
        for (int mi = 0; mi < 2; mi++)
            #pragma unroll
            for (int n = 0; n < 4; n++)
                #pragma unroll
                for (int c = 0; c < 4; c++) sc[mi][n][c] = 0.f;

        #pragma unroll
        for (int kk = 0; kk < 8; kk++) {
            float a[2][4];
            #pragma unroll
            for (int mi = 0; mi < 2; mi++) {
                int row = warp * 32 + mi * 16;
                a[mi][0] = Qs[(row + lr    ) * AS_STR + kk * 8 + lc    ];
                a[mi][1] = Qs[(row + lr + 8) * AS_STR + kk * 8 + lc    ];
                a[mi][2] = Qs[(row + lr    ) * AS_STR + kk * 8 + lc + 4];
                a[mi][3] = Qs[(row + lr + 8) * AS_STR + kk * 8 + lc + 4];
            }
            #pragma unroll
            for (int n = 0; n < 4; n++) {
                float b0 = kb[(n * 8 + lr) * AS_STR + kk * 8 + lc    ];
                float b1 = kb[(n * 8 + lr) * AS_STR + kk * 8 + lc + 4];
                mma16n8k8(sc[0][n], a[0], b0, b1);
                mma16n8k8(sc[1][n], a[1], b0, b1);
            }
        }

        // ---- online softmax per m-tile ----
        #pragma unroll
        for (int mi = 0; mi < 2; mi++) {
            float mx0 = -1e30f, mx1 = -1e30f;
            #pragma unroll
            for (int n = 0; n < 4; n++) {
                mx0 = fmaxf(mx0, fmaxf(sc[mi][n][0], sc[mi][n][1]));
                mx1 = fmaxf(mx1, fmaxf(sc[mi][n][2], sc[mi][n][3]));
            }
            #pragma unroll
            for (int m = 1; m <= 2; m <<= 1) {
                mx0 = fmaxf(mx0, __shfl_xor_sync(0xffffffffu, mx0, m));
                mx1 = fmaxf(mx1, __shfl_xor_sync(0xffffffffu, mx1, m));
            }
            float mn0 = fmaxf(mm[mi][0], mx0);
            float mn1 = fmaxf(mm[mi][1], mx1);
            float c0 = __expf(mm[mi][0] - mn0);
            float c1 = __expf(mm[mi][1] - mn1);
            mm[mi][0] = mn0; mm[mi][1] = mn1;
            ll[mi][0] *= c0; ll[mi][1] *= c1;
            #pragma unroll
            for (int n = 0; n < 8; n++) {
                o[mi][n][0] *= c0; o[mi][n][1] *= c0;
                o[mi][n][2] *= c1; o[mi][n][3] *= c1;
            }
            #pragma unroll
            for (int n = 0; n < 4; n++) {
                sc[mi][n][0] = __expf(sc[mi][n][0] - mn0);
                sc[mi][n][1] = __expf(sc[mi][n][1] - mn0);
                sc[mi][n][2] = __expf(sc[mi][n][2] - mn1);
                sc[mi][n][3] = __expf(sc[mi][n][3] - mn1);
                ll[mi][0] += sc[mi][n][0] + sc[mi][n][1];
                ll[mi][1] += sc[mi][n][2] + sc[mi][n][3];
            }
        }

        // ---- O += P V : fp16 m16n8k16, P A-frags direct from S C-frags ----
        #pragma unroll
        for (int kk = 0; kk < 2; kk++) {
            uint32_t pa[2][4];
            #pragma unroll
            for (int mi = 0; mi < 2; mi++) {
                pa[mi][0] = pack_half2(sc[mi][2*kk  ][0], sc[mi][2*kk  ][1]);
                pa[mi][1] = pack_half2(sc[mi][2*kk  ][2], sc[mi][2*kk  ][3]);
                pa[mi][2] = pack_half2(sc[mi][2*kk+1][0], sc[mi][2*kk+1][1]);
                pa[mi][3] = pack_half2(sc[mi][2*kk+1][2], sc[mi][2*kk+1][3]);
            }
            #pragma unroll
            for (int n = 0; n < 8; n++) {
                const __half* vrow = vb + (n * 8 + lr) * VS16_STR + kk * 16;
                uint32_t b0 = *(const uint32_t*)(vrow + 2 * lc);
                uint32_t b1 = *(const uint32_t*)(vrow + 2 * lc + 8);
                mma16n8k16_f16(o[0][n], pa[0], b0, b1);
                mma16n8k16_f16(o[1][n], pa[1], b0, b1);
            }
        }
        __syncthreads();
    }

    // ---- finalize: write fp32 tf32-rounded attn output ----
    #pragma unroll
    for (int mi = 0; mi < 2; mi++)
        #pragma unroll
        for (int half = 0; half < 2; half++)
            #pragma unroll
            for (int m = 1; m <= 2; m <<= 1)
                ll[mi][half] += __shfl_xor_sync(0xffffffffu, ll[mi][half], m);

    const int bb = bh / HH;
    const int hh = bh % HH;
    #pragma unroll
    for (int mi = 0; mi < 2; mi++) {
        #pragma unroll
        for (int half = 0; half < 2; half++) {
            float inv = 1.f / ll[mi][half];
            int row = qt0 + warp * 32 + mi * 16 + lr + half * 8;
            float* og = g_attn + ((size_t)bb * TT + row) * DD + hh * HS;
            #pragma unroll
            for (int n = 0; n < 8; n++) {
                *(float2*)(og + n * 8 + 2 * lc) =
                    make_float2(to_tf32(o[mi][n][half * 2]     * inv),
                                to_tf32(o[mi][n][half * 2 + 1] * inv));
            }
        }
    }
}

// ---------------------------------------------------------------------------
// Kernel 3: output projection — VERBATIM from the R7-passing tf32 version.
// ---------------------------------------------------------------------------
#define XS_STR 36
#define WS_STR 68
#define XS_BUF (128 * XS_STR)
#define WS_BUF (32 * WS_STR)

__global__ __launch_bounds__(128, 4) void oproj_mma_kernel(
    const float* __restrict__ bo,
    float* __restrict__ out)
{
    extern __shared__ float sm[];
    float* xs = sm;
    float* ws = sm + 2 * XS_BUF;

    const int tid  = threadIdx.x;
    const int lane = tid & 31;
    const int warp = tid >> 5;
    const int lr   = lane >> 2;
    const int lc   = lane & 3;
    const int m0   = blockIdx.x * 128;
    const int n0   = blockIdx.y * 64;

    const float* X = g_attn;
    const float* W = g_wo + n0;

    const uint32_t xs_s = (uint32_t)__cvta_generic_to_shared(xs);
    const uint32_t ws_s = (uint32_t)__cvta_generic_to_shared(ws);

    const int xr = tid >> 3, xc4 = tid & 7;
    const int wk = tid >> 4, we4 = tid & 15;

    #define OP_ISSUE(chunk, buf) do {                                           \
        int k0_ = (chunk) * 32;                                                 \
        _Pragma("unroll")                                                       \
        for (int it = 0; it < 8; it++) {                                        \
            int r = xr + it * 16;                                               \
            cpa16(xs_s + ((buf) * XS_BUF + r * XS_STR + xc4 * 4) * 4,           \
                  X + (size_t)(m0 + r) * DD + k0_ + xc4 * 4);                   \
        }                                                                       \
        _Pragma("unroll")                                                       \
        for (int it = 0; it < 4; it++) {                                        \
            int kk = wk + it * 8;                                               \
            cpa16(ws_s + ((buf) * WS_BUF + kk * WS_STR + we4 * 4) * 4,          \
                  W + (size_t)(k0_ + kk) * DD + we4 * 4);                       \
        }                                                                       \
    } while (0)

    float acc[2][8][4];
    #pragma unroll
    for (int mi = 0; mi < 2; mi++)
        #pragma unroll
        for (int n = 0; n < 8; n++)
            #pragma unroll
            for (int c = 0; c < 4; c++) acc[mi][n][c] = 0.f;

    OP_ISSUE(0, 0);
    cpa_commit();

    for (int c = 0; c < 16; c++) {
        int cur = c & 1;
        if (c < 15) { OP_ISSUE(c + 1, cur ^ 1); cpa_commit(); cpa_wait1(); }
        else        { cpa_wait0(); }
        __syncthreads();

        const float* xb = xs + cur * XS_BUF;
        const float* wb = ws + cur * WS_BUF;
        #pragma unroll
        for (int kk = 0; kk < 4; kk++) {
            float a[2][4];
            #pragma unroll
            for (int mi = 0; mi < 2; mi++) {
                int row = warp * 32 + mi * 16;
                a[mi][0] = xb[(row + lr    ) * XS_STR + kk * 8 + lc    ];
                a[mi][1] = xb[(row + lr + 8) * XS_STR + kk * 8 + lc    ];
                a[mi][2] = xb[(row + lr    ) * XS_STR + kk * 8 + lc + 4];
                a[mi][3] = xb[(row + lr + 8) * XS_STR + kk * 8 + lc + 4];
            }
            #pragma unroll
            for (int n = 0; n < 8; n++) {
                float b0 = wb[(kk * 8 + lc    ) * WS_STR + n * 8 + lr];
                float b1 = wb[(kk * 8 + lc + 4) * WS_STR + n * 8 + lr];
                mma16n8k8(acc[0][n], a[0], b0, b1);
                mma16n8k8(acc[1][n], a[1], b0, b1);
            }
        }
        __syncthreads();
    }

    #pragma unroll
    for (int mi = 0; mi < 2; mi++) {
        #pragma unroll
        for (int half = 0; half < 2; half++) {
            int m = m0 + warp * 32 + mi * 16 + lr + half * 8;
            float* og = out + (size_t)m * DD + n0;
            #pragma unroll
            for (int n = 0; n < 8; n++) {
                float2 bias = *(const float2*)(bo + n0 + n * 8 + 2 * lc);
                *(float2*)(og + n * 8 + 2 * lc) =
                    make_float2(acc[mi][n][half * 2]     + bias.x,
                                acc[mi][n][half * 2 + 1] + bias.y);
            }
        }
    }
}

// ---------------------------------------------------------------------------
extern "C" void kernel_launch(void* const* d_in, const int* in_sizes, int n_in,
                              void* d_out, int out_size)
{
    const float* x  = (const float*)d_in[0];
    const float* Wq = (const float*)d_in[1];
    const float* Wk = (const float*)d_in[2];
    const float* Wv = (const float*)d_in[3];
    const float* Wo = (const float*)d_in[4];
    const float* bo = (const float*)d_in[5];
    float* out = (float*)d_out;

    const int attn_smem = (Q_BUF + 2 * KV2_BUF) * 4 + 2 * VS16_BUF * 2;  // 62464 B
    const int op_smem   = 2 * (XS_BUF + WS_BUF) * 4;                     // 54272 B

    static bool attr_done = false;
    if (!attr_done) {
        cudaFuncSetAttribute(attn_mma_kernel,
            cudaFuncAttributeMaxDynamicSharedMemorySize, attn_smem);
        cudaFuncSetAttribute(oproj_mma_kernel,
            cudaFuncAttributeMaxDynamicSharedMemorySize, op_smem);
        attr_done = true;
    }

    x16_kernel<<<(BB*TT*DD/4)/256, 256>>>(x);

    dim3 gw(DD / 64, 3, HH);                 // (8, 3, 8)
    wqkv_trans16_kernel<<<gw, 256>>>(Wq, Wk, Wv);

    round_wo_kernel<<<(DD*DD/4)/256, 256>>>(Wo);

    dim3 g1((BB * TT) / 128, HH, 3);
    qkv_mma_kernel<<<g1, 256>>>();

    dim3 gv(TT / 64, BB * HH);
    vtrans_kernel<<<gv, 256>>>();

    dim3 g2(TT / 128, BB * HH);
    attn_mma_kernel<<<g2, 128, attn_smem>>>();

    dim3 g3((BB * TT) / 128, DD / 64);
    oproj_mma_kernel<<<g3, 128, op_smem>>>(bo, out);
}

// round 15
// speedup vs baseline: 1.6645x; 1.1443x over previous
#include <cuda_runtime.h>
#include <cuda_fp16.h>
#include <cstdint>

#define BB 4
#define TT 2048
#define DD 512
#define HH 8
#define HS 64

// Globals (allocation-free rule). Device globals are ONLY referenced from
// device code — never passed as kernel args from host (R8-R12 bug).
__device__ __half g_x16[BB*TT*DD];       // x, fp16
__device__ __half g_wq16t[HH*HS*DD];     // Wq^T per head: [h][e][d] fp16
__device__ __half g_wk16t[HH*HS*DD];
__device__ __half g_wv16t[HH*HS*DD];
__device__ __half g_wo16t[DD*DD];        // Wo^T: [n][k] fp16
__device__ float  g_q[BB*HH*TT*HS];      // [B,H,T,HS] tf32 values
__device__ float  g_k[BB*HH*TT*HS];
__device__ float  g_v[BB*HH*TT*HS];      // fp32 (feeds vtrans)
__device__ __half g_v16[BB*HH*HS*TT];    // [B,H,HS,T] fp16 (PV operand)
__device__ __half g_attn16[BB*TT*DD];    // [B,T,D] fp16 (oproj A operand)

// ---------------------------------------------------------------------------
// helpers
// ---------------------------------------------------------------------------
__device__ __forceinline__ float to_tf32(float x) {
    uint32_t u;
    asm("cvt.rna.tf32.f32 %0, %1;" : "=r"(u) : "f"(x));
    return __uint_as_float(u);
}

__device__ __forceinline__ void mma16n8k8(float c[4], const float a[4],
                                          float b0, float b1) {
    asm volatile(
        "mma.sync.aligned.m16n8k8.row.col.f32.tf32.tf32.f32 "
        "{%0,%1,%2,%3}, {%4,%5,%6,%7}, {%8,%9}, {%0,%1,%2,%3};"
        : "+f"(c[0]), "+f"(c[1]), "+f"(c[2]), "+f"(c[3])
        : "r"(__float_as_uint(a[0])), "r"(__float_as_uint(a[1])),
          "r"(__float_as_uint(a[2])), "r"(__float_as_uint(a[3])),
          "r"(__float_as_uint(b0)),  "r"(__float_as_uint(b1)));
}

__device__ __forceinline__ void mma16n8k16_f16(float c[4], const uint32_t a[4],
                                               uint32_t b0, uint32_t b1) {
    asm volatile(
        "mma.sync.aligned.m16n8k16.row.col.f32.f16.f16.f32 "
        "{%0,%1,%2,%3}, {%4,%5,%6,%7}, {%8,%9}, {%0,%1,%2,%3};"
        : "+f"(c[0]), "+f"(c[1]), "+f"(c[2]), "+f"(c[3])
        : "r"(a[0]), "r"(a[1]), "r"(a[2]), "r"(a[3]), "r"(b0), "r"(b1));
}

// pack (lo, hi) -> fp16x2 (lo in lower half)
__device__ __forceinline__ uint32_t pack_half2(float lo, float hi) {
    uint32_t r;
    asm("cvt.rn.f16x2.f32 %0, %1, %2;" : "=r"(r) : "f"(hi), "f"(lo));
    return r;
}

__device__ __forceinline__ void cpa16(uint32_t dst, const void* src) {
    asm volatile("cp.async.ca.shared.global [%0], [%1], 16;" :: "r"(dst), "l"(src));
}
__device__ __forceinline__ void cpa_commit() {
    asm volatile("cp.async.commit_group;");
}
__device__ __forceinline__ void cpa_wait0() {
    asm volatile("cp.async.wait_group 0;");
}
__device__ __forceinline__ void cpa_wait1() {
    asm volatile("cp.async.wait_group 1;");
}

// ---------------------------------------------------------------------------
// Prep 1: x fp32 -> fp16
// ---------------------------------------------------------------------------
__global__ __launch_bounds__(256) void x16_kernel(const float* __restrict__ x) {
    int i = blockIdx.x * 256 + threadIdx.x;    // float4 index
    float4 v = ((const float4*)x)[i];
    uint32_t h0 = pack_half2(v.x, v.y);
    uint32_t h1 = pack_half2(v.z, v.w);
    *(uint2*)(g_x16 + (size_t)i * 4) = make_uint2(h0, h1);
}

// ---------------------------------------------------------------------------
// Prep 2: Wq/Wk/Wv [h][d][e] fp32 -> g_w{q,k,v}16t [h][e][d] fp16.
// Destination selected DEVICE-SIDE from blockIdx.y.
// grid (DD/64=8, 3, HH=8), block 256.
// ---------------------------------------------------------------------------
__global__ __launch_bounds__(256) void wqkv_trans16_kernel(
    const float* __restrict__ Wq, const float* __restrict__ Wk,
    const float* __restrict__ Wv)
{
    __shared__ __half ts[64][72];
    const int tid  = threadIdx.x;
    const int r0   = blockIdx.x * 64;    // d-offset
    const int wsel = blockIdx.y;
    const int h    = blockIdx.z;

    const float* src = ((wsel == 0) ? Wq : (wsel == 1) ? Wk : Wv)
                       + (size_t)h * DD * HS;
    __half* dst = ((wsel == 0) ? g_wq16t : (wsel == 1) ? g_wk16t : g_wv16t)
                  + (size_t)h * HS * DD;

    #pragma unroll
    for (int it = 0; it < 4; it++) {
        int idx = tid + it * 256;          // 0..1023
        int r = idx >> 4, c4 = idx & 15;
        float4 v = *(const float4*)(src + (size_t)(r0 + r) * HS + c4 * 4);
        ts[c4*4+0][r] = __float2half_rn(v.x);
        ts[c4*4+1][r] = __float2half_rn(v.y);
        ts[c4*4+2][r] = __float2half_rn(v.z);
        ts[c4*4+3][r] = __float2half_rn(v.w);
    }
    __syncthreads();
    #pragma unroll
    for (int it = 0; it < 2; it++) {
        int idx = tid + it * 256;          // 0..511
        int e = idx >> 3, rc = idx & 7;
        *(uint4*)(dst + (size_t)e * DD + r0 + rc * 8) = *(uint4*)&ts[e][rc * 8];
    }
}

// ---------------------------------------------------------------------------
// Prep 2b: Wo [k][n] fp32 -> g_wo16t [n][k] fp16 (device-side global write).
// grid (DD/64=8 k-tiles, DD/64=8 n-tiles), block 256.
// ---------------------------------------------------------------------------
__global__ __launch_bounds__(256) void wo_trans16_kernel(const float* __restrict__ Wo)
{
    __shared__ __half ts[64][72];
    const int tid = threadIdx.x;
    const int k0  = blockIdx.x * 64;
    const int n0  = blockIdx.y * 64;

    #pragma unroll
    for (int it = 0; it < 4; it++) {
        int idx = tid + it * 256;          // 0..1023
        int r = idx >> 4, c4 = idx & 15;   // r: k-row, c4: n float4
        float4 v = *(const float4*)(Wo + (size_t)(k0 + r) * DD + n0 + c4 * 4);
        ts[c4*4+0][r] = __float2half_rn(v.x);
        ts[c4*4+1][r] = __float2half_rn(v.y);
        ts[c4*4+2][r] = __float2half_rn(v.z);
        ts[c4*4+3][r] = __float2half_rn(v.w);
    }
    __syncthreads();
    #pragma unroll
    for (int it = 0; it < 2; it++) {
        int idx = tid + it * 256;          // 0..511
        int n = idx >> 3, kc = idx & 7;
        *(uint4*)(g_wo16t + (size_t)(n0 + n) * DD + k0 + kc * 8) = *(uint4*)&ts[n][kc * 8];
    }
}

// ---------------------------------------------------------------------------
// Prep 3: V transpose/convert (VERBATIM from R7/R13-passing)
// ---------------------------------------------------------------------------
__global__ __launch_bounds__(256) void vtrans_kernel() {
    __shared__ __half ts[64][72];
    const int tid = threadIdx.x;
    const int bh  = blockIdx.y;
    const int t0  = blockIdx.x * 64;
    const float* vg = g_v + ((size_t)bh * TT + t0) * HS;

    #pragma unroll
    for (int it = 0; it < 4; it++) {
        int idx = tid + it * 256;
        int t = idx >> 4, e4 = idx & 15;
        float4 v = *(const float4*)(vg + t * HS + e4 * 4);
        ts[e4*4+0][t] = __float2half_rn(v.x);
        ts[e4*4+1][t] = __float2half_rn(v.y);
        ts[e4*4+2][t] = __float2half_rn(v.z);
        ts[e4*4+3][t] = __float2half_rn(v.w);
    }
    __syncthreads();
    __half* og = g_v16 + (size_t)bh * HS * TT + t0;
    #pragma unroll
    for (int it = 0; it < 2; it++) {
        int idx = tid + it * 256;
        int e = idx >> 3, tc = idx & 7;
        *(uint4*)(og + (size_t)e * TT + tc * 8) = *(uint4*)&ts[e][tc * 8];
    }
}

// ---------------------------------------------------------------------------
// Kernel 1: QKV projections, fp16 m16n8k16, 2 m-tiles/warp.
// 128 thr (4 warps), warp: 32 rows x 64 cols. k chunked by 32.
// Static smem 30.7 KB, u32 frag addressing. regs ~110, no cap -> no spill.
// grid (BT/128=64, H=8, 3).
// ---------------------------------------------------------------------------
__global__ __launch_bounds__(128) void qkv_mma_kernel()
{
    __shared__ uint32_t xs[2][128][20];   // 128 rows x 40 halfs
    __shared__ uint32_t ws[2][64][20];    // 64 n-rows x 40 halfs

    const int tid  = threadIdx.x;
    const int lane = tid & 31;
    const int warp = tid >> 5;            // 0..3 -> 32-row m-tile pair
    const int lr   = lane >> 2;
    const int lc   = lane & 3;
    const int m0   = blockIdx.x * 128;
    const int h    = blockIdx.y;
    const int wsel = blockIdx.z;

    const __half* X16 = g_x16;
    const __half* W16 = ((wsel == 0) ? g_wq16t : (wsel == 1) ? g_wk16t : g_wv16t)
                        + (size_t)h * HS * DD;
    float* out = (wsel == 0) ? g_q : (wsel == 1) ? g_k : g_v;

    // cp.async slots (128 thr): x = 512 chunks -> 4/thread; w = 256 -> 2/thread
    const int cr = tid >> 2, cc = tid & 3;

    #define QKV_ISSUE(chunk, buf) do {                                          \
        int k0_ = (chunk) * 32;                                                 \
        _Pragma("unroll")                                                       \
        for (int it = 0; it < 4; it++) {                                        \
            int r = cr + it * 32;                                               \
            cpa16((uint32_t)__cvta_generic_to_shared(&xs[buf][r][cc * 4]),      \
                  X16 + (size_t)(m0 + r) * DD + k0_ + cc * 8);                  \
        }                                                                       \
        _Pragma("unroll")                                                       \
        for (int it = 0; it < 2; it++) {                                        \
            int n = cr + it * 32;                                               \
            cpa16((uint32_t)__cvta_generic_to_shared(&ws[buf][n][cc * 4]),      \
                  W16 + (size_t)n * DD + k0_ + cc * 8);                         \
        }                                                                       \
    } while (0)

    float acc[2][8][4];
    #pragma unroll
    for (int mi = 0; mi < 2; mi++)
        #pragma unroll
        for (int n = 0; n < 8; n++)
            #pragma unroll
            for (int c = 0; c < 4; c++) acc[mi][n][c] = 0.f;

    QKV_ISSUE(0, 0);
    cpa_commit();

    for (int c = 0; c < 16; c++) {
        int cur = c & 1;
        if (c < 15) { QKV_ISSUE(c + 1, cur ^ 1); cpa_commit(); cpa_wait1(); }
        else        { cpa_wait0(); }
        __syncthreads();

        #pragma unroll
        for (int ks = 0; ks < 2; ks++) {
            uint32_t a[2][4];
            #pragma unroll
            for (int mi = 0; mi < 2; mi++) {
                int row = warp * 32 + mi * 16;
                a[mi][0] = xs[cur][row + lr    ][ks * 8 + lc    ];
                a[mi][1] = xs[cur][row + lr + 8][ks * 8 + lc    ];
                a[mi][2] = xs[cur][row + lr    ][ks * 8 + lc + 4];
                a[mi][3] = xs[cur][row + lr + 8][ks * 8 + lc + 4];
            }
            #pragma unroll
            for (int n = 0; n < 8; n++) {
                uint32_t b0 = ws[cur][n * 8 + lr][ks * 8 + lc    ];
                uint32_t b1 = ws[cur][n * 8 + lr][ks * 8 + lc + 4];
                mma16n8k16_f16(acc[0][n], a[0], b0, b1);
                mma16n8k16_f16(acc[1][n], a[1], b0, b1);
            }
        }
        __syncthreads();
    }

    // epilogue: write tf32-rounded fp32 (attention QK consumes without cvt)
    #pragma unroll
    for (int mi = 0; mi < 2; mi++) {
        #pragma unroll
        for (int half = 0; half < 2; half++) {
            int m = m0 + warp * 32 + mi * 16 + lr + half * 8;
            int bb = m >> 11;
            int t  = m & (TT - 1);
            float* og = out + ((size_t)(bb * HH + h) * TT + t) * HS;
            #pragma unroll
            for (int n = 0; n < 8; n++) {
                *(float2*)(og + n * 8 + 2 * lc) =
                    make_float2(to_tf32(acc[mi][n][half * 2]),
                                to_tf32(acc[mi][n][half * 2 + 1]));
            }
        }
    }
}

// ---------------------------------------------------------------------------
// Kernel 2: flash attention — R13-passing version; ONLY the finalize changes:
// writes g_attn16 fp16 (oproj A operand) instead of fp32 g_attn.
// ---------------------------------------------------------------------------
#define AS_STR   68
#define Q_BUF    (128 * AS_STR)
#define KV2_BUF  (32 * AS_STR)
#define VS16_STR 40
#define VS16_BUF (64 * VS16_STR)
#define KT2      32

__global__ __launch_bounds__(128, 3) void attn_mma_kernel()
{
    extern __shared__ float sm[];
    float*  Qs   = sm;                              // [128][68] (scaled 1/8)
    float*  Ks   = sm + Q_BUF;                      // [2][32][68]
    __half* Vs16 = (__half*)(sm + Q_BUF + 2 * KV2_BUF);  // [2][64][40]

    const int tid  = threadIdx.x;
    const int lane = tid & 31;
    const int warp = tid >> 5;
    const int lr   = lane >> 2;
    const int lc   = lane & 3;
    const int bh   = blockIdx.y;
    const int qt0  = blockIdx.x * 128;

    const float*  qg   = g_q + ((size_t)bh * TT + qt0) * HS;
    const float*  kg   = g_k + (size_t)bh * TT * HS;
    const __half* vg16 = g_v16 + (size_t)bh * HS * TT;

    const uint32_t ks_s = (uint32_t)__cvta_generic_to_shared(Ks);
    const uint32_t vs_s = (uint32_t)__cvta_generic_to_shared(Vs16);

    const int kvr = tid >> 4, kvc4 = tid & 15;
    const int ve  = tid >> 2, vkc  = tid & 3;

    #define ATTN_ISSUE_KV(tile, buf) do {                                       \
        int t0_ = (tile) * KT2;                                                 \
        _Pragma("unroll")                                                       \
        for (int it = 0; it < 4; it++) {                                        \
            int r = kvr + it * 8;                                               \
            cpa16(ks_s + ((buf) * KV2_BUF + r * AS_STR + kvc4 * 4) * 4,         \
                  kg + (size_t)(t0_ + r) * HS + kvc4 * 4);                      \
        }                                                                       \
        _Pragma("unroll")                                                       \
        for (int it = 0; it < 2; it++) {                                        \
            int e = ve + it * 32;                                               \
            cpa16(vs_s + ((buf) * VS16_BUF + e * VS16_STR + vkc * 8) * 2,       \
                  vg16 + (size_t)e * TT + t0_ + vkc * 8);                       \
        }                                                                       \
    } while (0)

    ATTN_ISSUE_KV(0, 0);
    cpa_commit();
    #pragma unroll
    for (int it = 0; it < 16; it++) {
        int idx = tid + it * 128;
        int r = idx >> 4, c4 = idx & 15;
        float4 v = *(const float4*)(qg + (size_t)r * HS + c4 * 4);
        v.x *= 0.125f; v.y *= 0.125f; v.z *= 0.125f; v.w *= 0.125f;
        *(float4*)&Qs[r * AS_STR + c4 * 4] = v;
    }
    cpa_wait0();
    __syncthreads();

    float o[2][8][4];
    float mm[2][2], ll[2][2];
    #pragma unroll
    for (int mi = 0; mi < 2; mi++) {
        #pragma unroll
        for (int n = 0; n < 8; n++)
            #pragma unroll
            for (int c = 0; c < 4; c++) o[mi][n][c] = 0.f;
        mm[mi][0] = mm[mi][1] = -1e30f;
        ll[mi][0] = ll[mi][1] = 0.f;
    }

    for (int t = 0; t < TT / KT2; t++) {
        int cur = t & 1;
        if (t < TT / KT2 - 1) { ATTN_ISSUE_KV(t + 1, cur ^ 1); cpa_commit(); cpa_wait1(); }
        else                  { cpa_wait0(); }
        __syncthreads();

        const float*  kb = Ks + cur * KV2_BUF;
        const __half* vb = Vs16 + cur * VS16_BUF;

        float sc[2][4][4];
        #pragma unroll
        for (int mi = 0; mi < 2; mi++)
            #pragma unroll
            for (int n = 0; n < 4; n++)
                #pragma unroll
                for (int c = 0; c < 4; c++) sc[mi][n][c] = 0.f;

        #pragma unroll
        for (int kk = 0; kk < 8; kk++) {
            float a[2][4];
            #pragma unroll
            for (int mi = 0; mi < 2; mi++) {
                int row = warp * 32 + mi * 16;
                a[mi][0] = Qs[(row + lr    ) * AS_STR + kk * 8 + lc    ];
                a[mi][1] = Qs[(row + lr + 8) * AS_STR + kk * 8 + lc    ];
                a[mi][2] = Qs[(row + lr    ) * AS_STR + kk * 8 + lc + 4];
                a[mi][3] = Qs[(row + lr + 8) * AS_STR + kk * 8 + lc + 4];
            }
            #pragma unroll
            for (int n = 0; n < 4; n++) {
                float b0 = kb[(n * 8 + lr) * AS_STR + kk * 8 + lc    ];
                float b1 = kb[(n * 8 + lr) * AS_STR + kk * 8 + lc + 4];
                mma16n8k8(sc[0][n], a[0], b0, b1);
                mma16n8k8(sc[1][n], a[1], b0, b1);
            }
        }

        #pragma unroll
        for (int mi = 0; mi < 2; mi++) {
            float mx0 = -1e30f, mx1 = -1e30f;
            #pragma unroll
            for (int n = 0; n < 4; n++) {
                mx0 = fmaxf(mx0, fmaxf(sc[mi][n][0], sc[mi][n][1]));
                mx1 = fmaxf(mx1, fmaxf(sc[mi][n][2], sc[mi][n][3]));
            }
            #pragma unroll
            for (int m = 1; m <= 2; m <<= 1) {
                mx0 = fmaxf(mx0, __shfl_xor_sync(0xffffffffu, mx0, m));
                mx1 = fmaxf(mx1, __shfl_xor_sync(0xffffffffu, mx1, m));
            }
            float mn0 = fmaxf(mm[mi][0], mx0);
            float mn1 = fmaxf(mm[mi][1], mx1);
            float c0 = __expf(mm[mi][0] - mn0);
            float c1 = __expf(mm[mi][1] - mn1);
            mm[mi][0] = mn0; mm[mi][1] = mn1;
            ll[mi][0] *= c0; ll[mi][1] *= c1;
            #pragma unroll
            for (int n = 0; n < 8; n++) {
                o[mi][n][0] *= c0; o[mi][n][1] *= c0;
                o[mi][n][2] *= c1; o[mi][n][3] *= c1;
            }
            #pragma unroll
            for (int n = 0; n < 4; n++) {
                sc[mi][n][0] = __expf(sc[mi][n][0] - mn0);
                sc[mi][n][1] = __expf(sc[mi][n][1] - mn0);
                sc[mi][n][2] = __expf(sc[mi][n][2] - mn1);
                sc[mi][n][3] = __expf(sc[mi][n][3] - mn1);
                ll[mi][0] += sc[mi][n][0] + sc[mi][n][1];
                ll[mi][1] += sc[mi][n][2] + sc[mi][n][3];
            }
        }

        #pragma unroll
        for (int kk = 0; kk < 2; kk++) {
            uint32_t pa[2][4];
            #pragma unroll
            for (int mi = 0; mi < 2; mi++) {
                pa[mi][0] = pack_half2(sc[mi][2*kk  ][0], sc[mi][2*kk  ][1]);
                pa[mi][1] = pack_half2(sc[mi][2*kk  ][2], sc[mi][2*kk  ][3]);
                pa[mi][2] = pack_half2(sc[mi][2*kk+1][0], sc[mi][2*kk+1][1]);
                pa[mi][3] = pack_half2(sc[mi][2*kk+1][2], sc[mi][2*kk+1][3]);
            }
            #pragma unroll
            for (int n = 0; n < 8; n++) {
                const __half* vrow = vb + (n * 8 + lr) * VS16_STR + kk * 16;
                uint32_t b0 = *(const uint32_t*)(vrow + 2 * lc);
                uint32_t b1 = *(const uint32_t*)(vrow + 2 * lc + 8);
                mma16n8k16_f16(o[0][n], pa[0], b0, b1);
                mma16n8k16_f16(o[1][n], pa[1], b0, b1);
            }
        }
        __syncthreads();
    }

    // ---- finalize: write fp16 attn output (oproj A operand) ----
    #pragma unroll
    for (int mi = 0; mi < 2; mi++)
        #pragma unroll
        for (int half = 0; half < 2; half++)
            #pragma unroll
            for (int m = 1; m <= 2; m <<= 1)
                ll[mi][half] += __shfl_xor_sync(0xffffffffu, ll[mi][half], m);

    const int bb = bh / HH;
    const int hh = bh % HH;
    #pragma unroll
    for (int mi = 0; mi < 2; mi++) {
        #pragma unroll
        for (int half = 0; half < 2; half++) {
            float inv = 1.f / ll[mi][half];
            int row = qt0 + warp * 32 + mi * 16 + lr + half * 8;
            __half* og = g_attn16 + ((size_t)bb * TT + row) * DD + hh * HS;
            #pragma unroll
            for (int n = 0; n < 8; n++) {
                *(uint32_t*)(og + n * 8 + 2 * lc) =
                    pack_half2(o[mi][n][half * 2]     * inv,
                               o[mi][n][half * 2 + 1] * inv);
            }
        }
    }
}

// ---------------------------------------------------------------------------
// Kernel 3: output projection, fp16 m16n8k16 — structural clone of kernel 1
// (+bias epilogue). 128 thr, 2 m-tiles/warp. grid (BT/128=64, DD/64=8).
// ---------------------------------------------------------------------------
__global__ __launch_bounds__(128) void oproj_mma_kernel(
    const float* __restrict__ bo,
    float* __restrict__ out)
{
    __shared__ uint32_t xs[2][128][20];
    __shared__ uint32_t ws[2][64][20];

    const int tid  = threadIdx.x;
    const int lane = tid & 31;
    const int warp = tid >> 5;
    const int lr   = lane >> 2;
    const int lc   = lane & 3;
    const int m0   = blockIdx.x * 128;
    const int n0   = blockIdx.y * 64;

    const __half* X16 = g_attn16;
    const __half* W16 = g_wo16t + (size_t)n0 * DD;

    const int cr = tid >> 2, cc = tid & 3;

    #define OP_ISSUE(chunk, buf) do {                                           \
        int k0_ = (chunk) * 32;                                                 \
        _Pragma("unroll")                                                       \
        for (int it = 0; it < 4; it++) {                                        \
            int r = cr + it * 32;                                               \
            cpa16((uint32_t)__cvta_generic_to_shared(&xs[buf][r][cc * 4]),      \
                  X16 + (size_t)(m0 + r) * DD + k0_ + cc * 8);                  \
        }                                                                       \
        _Pragma("unroll")                                                       \
        for (int it = 0; it < 2; it++) {                                        \
            int n = cr + it * 32;                                               \
            cpa16((uint32_t)__cvta_generic_to_shared(&ws[buf][n][cc * 4]),      \
                  W16 + (size_t)n * DD + k0_ + cc * 8);                         \
        }                                                                       \
    } while (0)

    float acc[2][8][4];
    #pragma unroll
    for (int mi = 0; mi < 2; mi++)
        #pragma unroll
        for (int n = 0; n < 8; n++)
            #pragma unroll
            for (int c = 0; c < 4; c++) acc[mi][n][c] = 0.f;

    OP_ISSUE(0, 0);
    cpa_commit();

    for (int c = 0; c < 16; c++) {
        int cur = c & 1;
        if (c < 15) { OP_ISSUE(c + 1, cur ^ 1); cpa_commit(); cpa_wait1(); }
        else        { cpa_wait0(); }
        __syncthreads();

        #pragma unroll
        for (int ks = 0; ks < 2; ks++) {
            uint32_t a[2][4];
            #pragma unroll
            for (int mi = 0; mi < 2; mi++) {
                int row = warp * 32 + mi * 16;
                a[mi][0] = xs[cur][row + lr    ][ks * 8 + lc    ];
                a[mi][1] = xs[cur][row + lr + 8][ks * 8 + lc    ];
                a[mi][2] = xs[cur][row + lr    ][ks * 8 + lc + 4];
                a[mi][3] = xs[cur][row + lr + 8][ks * 8 + lc + 4];
            }
            #pragma unroll
            for (int n = 0; n < 8; n++) {
                uint32_t b0 = ws[cur][n * 8 + lr][ks * 8 + lc    ];
                uint32_t b1 = ws[cur][n * 8 + lr][ks * 8 + lc + 4];
                mma16n8k16_f16(acc[0][n], a[0], b0, b1);
                mma16n8k16_f16(acc[1][n], a[1], b0, b1);
            }
        }
        __syncthreads();
    }

    #pragma unroll
    for (int mi = 0; mi < 2; mi++) {
        #pragma unroll
        for (int half = 0; half < 2; half++) {
            int m = m0 + warp * 32 + mi * 16 + lr + half * 8;
            float* og = out + (size_t)m * DD + n0;
            #pragma unroll
            for (int n = 0; n < 8; n++) {
                float2 bias = *(const float2*)(bo + n0 + n * 8 + 2 * lc);
                *(float2*)(og + n * 8 + 2 * lc) =
                    make_float2(acc[mi][n][half * 2]     + bias.x,
                                acc[mi][n][half * 2 + 1] + bias.y);
            }
        }
    }
}

// ---------------------------------------------------------------------------
extern "C" void kernel_launch(void* const* d_in, const int* in_sizes, int n_in,
                              void* d_out, int out_size)
{
    const float* x  = (const float*)d_in[0];
    const float* Wq = (const float*)d_in[1];
    const float* Wk = (const float*)d_in[2];
    const float* Wv = (const float*)d_in[3];
    const float* Wo = (const float*)d_in[4];
    const float* bo = (const float*)d_in[5];
    float* out = (float*)d_out;

    const int attn_smem = (Q_BUF + 2 * KV2_BUF) * 4 + 2 * VS16_BUF * 2;  // 62464 B

    static bool attr_done = false;
    if (!attr_done) {
        cudaFuncSetAttribute(attn_mma_kernel,
            cudaFuncAttributeMaxDynamicSharedMemorySize, attn_smem);
        attr_done = true;
    }

    x16_kernel<<<(BB*TT*DD/4)/256, 256>>>(x);

    dim3 gw(DD / 64, 3, HH);                 // (8, 3, 8)
    wqkv_trans16_kernel<<<gw, 256>>>(Wq, Wk, Wv);

    dim3 gwo(DD / 64, DD / 64);              // (8, 8)
    wo_trans16_kernel<<<gwo, 256>>>(Wo);

    dim3 g1((BB * TT) / 128, HH, 3);
    qkv_mma_kernel<<<g1, 128>>>();

    dim3 gv(TT / 64, BB * HH);
    vtrans_kernel<<<gv, 256>>>();

    dim3 g2(TT / 128, BB * HH);
    attn_mma_kernel<<<g2, 128, attn_smem>>>();

    dim3 g3((BB * TT) / 128, DD / 64);
    oproj_mma_kernel<<<g3, 128>>>(bo, out);
}